// round 1
// baseline (speedup 1.0000x reference)
#include <cuda_runtime.h>
#include <float.h>

// AFM fused kernel.
// out[b] = bl + sum_p softmax_p(l_p) * s_p
//   s_p = (x[b,r]∘x[b,c])·Wl
//   l_p = W2·relu(W1·(x[b,r]∘x[b,c]) + b1) + b2
//
// One block per batch element. x[b] and W1 staged in shared memory.
// Thread-per-pair; per-pair 64-reg inner vector; 4-h-blocked GEMV with
// float4 broadcast loads of W1 rows. Online softmax reduced across block.

namespace {

constexpr int NF    = 40;
constexpr int ED    = 64;
constexpr int NPAIR = NF * (NF - 1) / 2;  // 780
constexpr int NT    = 256;

__global__ __launch_bounds__(NT, 2)
void afm_kernel(const float* __restrict__ x,
                const float* __restrict__ W1,
                const float* __restrict__ b1,
                const float* __restrict__ W2,
                const float* __restrict__ b2,
                const float* __restrict__ Wl,
                const float* __restrict__ bl,
                float* __restrict__ out)
{
    __shared__ float sx[NF][ED + 1];   // 65-float rows: conflict-free row gather
    __shared__ float sW1[ED][ED];
    __shared__ float sb1[ED];
    __shared__ float sW2[ED];
    __shared__ float sWl[ED];
    __shared__ float sb2s, sbls;
    __shared__ float rm[8], rz[8], rs[8];

    const int tid = threadIdx.x;
    const int b   = blockIdx.x;

    // ---- stage inputs ----
    const float* xb = x + (long)b * NF * ED;
    for (int i = tid; i < NF * ED; i += NT) sx[i >> 6][i & 63] = xb[i];
    for (int i = tid; i < ED * ED; i += NT) (&sW1[0][0])[i] = W1[i];
    if (tid < ED) { sb1[tid] = b1[tid]; sW2[tid] = W2[tid]; sWl[tid] = Wl[tid]; }
    if (tid == 0) { sb2s = b2[0]; sbls = bl[0]; }
    __syncthreads();

    // ---- per-thread online softmax state ----
    float m = -FLT_MAX, Z = 0.f, S = 0.f;
    const float b2v = sb2s;

    for (int p = tid; p < NPAIR; p += NT) {
        // decode pair index -> (r, c), row-major upper triangle k=1
        int pp = p, r = 0;
        while (pp >= NF - 1 - r) { pp -= NF - 1 - r; ++r; }
        const int c = r + 1 + pp;

        // inner vector in registers + s_p = inner · Wl
        float inner[ED];
        float sval = 0.f;
        #pragma unroll
        for (int e = 0; e < ED; ++e) {
            float v = sx[r][e] * sx[c][e];
            inner[e] = v;
            sval = fmaf(v, sWl[e], sval);
        }

        // logit = W2 · relu(W1 · inner + b1) + b2, 4 h-rows at a time
        float logit = b2v;
        for (int h = 0; h < ED; h += 4) {
            float a0 = sb1[h + 0];
            float a1 = sb1[h + 1];
            float a2 = sb1[h + 2];
            float a3 = sb1[h + 3];
            #pragma unroll
            for (int e4 = 0; e4 < ED / 4; ++e4) {
                const float4 w0 = *(const float4*)&sW1[h + 0][e4 * 4];
                const float4 w1 = *(const float4*)&sW1[h + 1][e4 * 4];
                const float4 w2 = *(const float4*)&sW1[h + 2][e4 * 4];
                const float4 w3 = *(const float4*)&sW1[h + 3][e4 * 4];
                const float i0 = inner[e4 * 4 + 0];
                const float i1 = inner[e4 * 4 + 1];
                const float i2 = inner[e4 * 4 + 2];
                const float i3 = inner[e4 * 4 + 3];
                a0 = fmaf(i0, w0.x, a0); a0 = fmaf(i1, w0.y, a0);
                a0 = fmaf(i2, w0.z, a0); a0 = fmaf(i3, w0.w, a0);
                a1 = fmaf(i0, w1.x, a1); a1 = fmaf(i1, w1.y, a1);
                a1 = fmaf(i2, w1.z, a1); a1 = fmaf(i3, w1.w, a1);
                a2 = fmaf(i0, w2.x, a2); a2 = fmaf(i1, w2.y, a2);
                a2 = fmaf(i2, w2.z, a2); a2 = fmaf(i3, w2.w, a2);
                a3 = fmaf(i0, w3.x, a3); a3 = fmaf(i1, w3.y, a3);
                a3 = fmaf(i2, w3.z, a3); a3 = fmaf(i3, w3.w, a3);
            }
            logit = fmaf(fmaxf(a0, 0.f), sW2[h + 0], logit);
            logit = fmaf(fmaxf(a1, 0.f), sW2[h + 1], logit);
            logit = fmaf(fmaxf(a2, 0.f), sW2[h + 2], logit);
            logit = fmaf(fmaxf(a3, 0.f), sW2[h + 3], logit);
        }

        // online softmax accumulate
        const float mn = fmaxf(m, logit);
        const float sc = __expf(m - mn);
        const float w  = __expf(logit - mn);
        Z = Z * sc + w;
        S = S * sc + sval * w;
        m = mn;
    }

    // ---- block reduction of (m, Z, S) ----
    #pragma unroll
    for (int off = 16; off; off >>= 1) {
        const float m2 = __shfl_down_sync(0xffffffffu, m, off);
        const float Z2 = __shfl_down_sync(0xffffffffu, Z, off);
        const float S2 = __shfl_down_sync(0xffffffffu, S, off);
        const float mn = fmaxf(m, m2);
        const float e1 = __expf(m - mn);
        const float e2 = __expf(m2 - mn);
        Z = Z * e1 + Z2 * e2;
        S = S * e1 + S2 * e2;
        m = mn;
    }
    const int wid = tid >> 5, lid = tid & 31;
    if (lid == 0) { rm[wid] = m; rz[wid] = Z; rs[wid] = S; }
    __syncthreads();
    if (wid == 0) {
        m = (lid < 8) ? rm[lid] : -FLT_MAX;
        Z = (lid < 8) ? rz[lid] : 0.f;
        S = (lid < 8) ? rs[lid] : 0.f;
        #pragma unroll
        for (int off = 4; off; off >>= 1) {
            const float m2 = __shfl_down_sync(0xffffffffu, m, off);
            const float Z2 = __shfl_down_sync(0xffffffffu, Z, off);
            const float S2 = __shfl_down_sync(0xffffffffu, S, off);
            const float mn = fmaxf(m, m2);
            const float e1 = __expf(m - mn);
            const float e2 = __expf(m2 - mn);
            Z = Z * e1 + Z2 * e2;
            S = S * e1 + S2 * e2;
            m = mn;
        }
        if (lid == 0) out[b] = S / Z + sbls;
    }
}

}  // namespace

extern "C" void kernel_launch(void* const* d_in, const int* in_sizes, int n_in,
                              void* d_out, int out_size)
{
    const float* x  = (const float*)d_in[0];
    const float* W1 = (const float*)d_in[1];
    const float* b1 = (const float*)d_in[2];
    const float* W2 = (const float*)d_in[3];
    const float* b2 = (const float*)d_in[4];
    const float* Wl = (const float*)d_in[5];
    const float* bl = (const float*)d_in[6];
    float* out = (float*)d_out;

    const int batch = in_sizes[0] / (NF * ED);  // 2048
    afm_kernel<<<batch, NT>>>(x, W1, b1, W2, b2, Wl, bl, out);
}

// round 3
// speedup vs baseline: 2.8371x; 2.8371x over previous
#include <cuda_runtime.h>
#include <cuda_bf16.h>
#include <cstdint>
#include <float.h>

// AFM fused kernel — warp-level mma.sync (HMMA bf16, hi/lo split) edition.
//
// out[b] = bl + sum_p softmax_p(l_p) * s_p
//   inner_p = x[b,r]∘x[b,c]
//   s_p = inner_p·Wl                       (fp32, during A-fragment build)
//   l_p = W2·relu(W1·inner_p + b1) + b2    (W1 GEMM via mma.sync bf16 3-term split)
//
// One CTA per batch element, 8 warps. 780 pairs -> 49 M-tiles of 16.
// Each warp independently: builds A fragments in registers, runs
// 8(n) x 4(k) x 3(split) mma.sync.m16n8k16, epilogues to logits/svals in smem.
// Then block-wide online softmax over 780 logits.

namespace {

constexpr int NF    = 40;
constexpr int ED    = 64;
constexpr int NPAIR = NF * (NF - 1) / 2;   // 780
constexpr int NTILE = (NPAIR + 15) / 16;   // 49
constexpr int NPAD  = NTILE * 16;          // 784
constexpr int NT    = 256;

// hi = bf16 truncation (RZ); lo = residual. Returns packed {v1_hi, v0_hi}.
__device__ __forceinline__ uint32_t pack_hi2(float v0, float v1, float& l0, float& l1) {
    const uint32_t u0 = __float_as_uint(v0) & 0xffff0000u;
    const uint32_t u1 = __float_as_uint(v1) & 0xffff0000u;
    l0 = v0 - __uint_as_float(u0);
    l1 = v1 - __uint_as_float(u1);
    return __byte_perm(u0, u1, 0x7632);  // bytes: [u0.b2, u0.b3, u1.b2, u1.b3]
}
__device__ __forceinline__ uint32_t pack_bf2(float l0, float l1) {
    uint32_t r;
    asm("cvt.rn.bf16x2.f32 %0, %1, %2;" : "=r"(r) : "f"(l1), "f"(l0));
    return r;
}

__device__ __forceinline__ void mma16816(float* c, uint32_t a0, uint32_t a1,
                                         uint32_t a2, uint32_t a3,
                                         uint32_t b0, uint32_t b1) {
    asm volatile(
        "mma.sync.aligned.m16n8k16.row.col.f32.bf16.bf16.f32 "
        "{%0,%1,%2,%3}, {%4,%5,%6,%7}, {%8,%9}, {%0,%1,%2,%3};"
        : "+f"(c[0]), "+f"(c[1]), "+f"(c[2]), "+f"(c[3])
        : "r"(a0), "r"(a1), "r"(a2), "r"(a3), "r"(b0), "r"(b1));
}

__global__ __launch_bounds__(NT, 2)
void afm_mma_kernel(const float* __restrict__ x,
                    const float* __restrict__ W1,
                    const float* __restrict__ b1,
                    const float* __restrict__ W2,
                    const float* __restrict__ b2,
                    const float* __restrict__ Wl,
                    const float* __restrict__ bl,
                    float* __restrict__ out)
{
    __shared__ __align__(16) float    sx[NF * 66];       // [40][66] padded rows
    __shared__           uint32_t sW1h[ED][36];          // packed bf16x2, stride 36 words
    __shared__           uint32_t sW1l[ED][36];          //   -> bank = 4*gid + t (conflict-free)
    __shared__ __align__(16) float    sb1[ED];
    __shared__ __align__(16) float    sW2[ED];
    __shared__ __align__(16) float    sWl[ED];
    __shared__           float    logits[NPAD];
    __shared__           float    svals[NPAD];
    __shared__           uint32_t pairs[NPAD];
    __shared__           float    red[24];
    __shared__           float    scal2[2];

    const int tid = threadIdx.x;
    const int wid = tid >> 5, lid = tid & 31;
    const int gid = lid >> 2, t = lid & 3;
    const int b = blockIdx.x;

    // ---- stage x[b] ----
    const float* xb = x + (long)b * NF * ED;
    for (int i = tid; i < NF * ED; i += NT) sx[(i >> 6) * 66 + (i & 63)] = xb[i];

    // ---- stage W1 as hi/lo packed bf16x2 ----
    for (int i = tid; i < ED * 32; i += NT) {
        const int h = i >> 5, w = i & 31;
        const float2 v = *(const float2*)(W1 + h * 64 + 2 * w);
        float l0, l1;
        const uint32_t hi = pack_hi2(v.x, v.y, l0, l1);
        sW1h[h][w] = hi;
        sW1l[h][w] = pack_bf2(l0, l1);
    }
    if (tid < ED) { sb1[tid] = b1[tid]; sW2[tid] = W2[tid]; sWl[tid] = Wl[tid]; }
    if (tid == 0) { scal2[0] = b2[0]; scal2[1] = bl[0]; }

    // ---- pair index table ----
    for (int p = tid; p < NPAD; p += NT) {
        if (p < NPAIR) {
            int r = 0, rem = p;
            while (rem >= NF - 1 - r) { rem -= NF - 1 - r; ++r; }
            pairs[p] = ((uint32_t)r << 8) | (uint32_t)(r + 1 + rem);
        } else {
            pairs[p] = 1u;  // dummy (0,1)
        }
    }
    __syncthreads();

    const float b2v = scal2[0], blv = scal2[1];

    // ---- per-warp independent M-tiles ----
    for (int tile = wid; tile < NTILE; tile += 8) {
        const int tb = tile * 16;
        const int p0 = tb + gid, p1 = p0 + 8;

        const uint32_t rc0 = pairs[p0], rc1 = pairs[p1];
        const float* xr0 = sx + (rc0 >> 8) * 66;
        const float* xc0 = sx + (rc0 & 255u) * 66;
        const float* xr1 = sx + (rc1 >> 8) * 66;
        const float* xc1 = sx + (rc1 & 255u) * 66;

        // A fragments (hi/lo) + s_p partials
        uint32_t raH[16], raL[16];
        float s0 = 0.f, s1 = 0.f;
        #pragma unroll
        for (int kk = 0; kk < 4; ++kk) {
            const int e = kk * 16 + 2 * t;
            const float2 wla = *(const float2*)&sWl[e];
            const float2 wlb = *(const float2*)&sWl[e + 8];

            float2 a, c;
            a = *(const float2*)(xr0 + e);     c = *(const float2*)(xc0 + e);
            const float v0 = a.x * c.x, v1 = a.y * c.y;
            a = *(const float2*)(xr0 + e + 8); c = *(const float2*)(xc0 + e + 8);
            const float v2 = a.x * c.x, v3 = a.y * c.y;
            a = *(const float2*)(xr1 + e);     c = *(const float2*)(xc1 + e);
            const float v4 = a.x * c.x, v5 = a.y * c.y;
            a = *(const float2*)(xr1 + e + 8); c = *(const float2*)(xc1 + e + 8);
            const float v6 = a.x * c.x, v7 = a.y * c.y;

            s0 = fmaf(v0, wla.x, s0); s0 = fmaf(v1, wla.y, s0);
            s0 = fmaf(v2, wlb.x, s0); s0 = fmaf(v3, wlb.y, s0);
            s1 = fmaf(v4, wla.x, s1); s1 = fmaf(v5, wla.y, s1);
            s1 = fmaf(v6, wlb.x, s1); s1 = fmaf(v7, wlb.y, s1);

            float l0, l1;
            // frag order: {row gid, col 2t}, {row gid+8, col 2t}, {gid, 2t+8}, {gid+8, 2t+8}
            raH[kk * 4 + 0] = pack_hi2(v0, v1, l0, l1); raL[kk * 4 + 0] = pack_bf2(l0, l1);
            raH[kk * 4 + 1] = pack_hi2(v4, v5, l0, l1); raL[kk * 4 + 1] = pack_bf2(l0, l1);
            raH[kk * 4 + 2] = pack_hi2(v2, v3, l0, l1); raL[kk * 4 + 2] = pack_bf2(l0, l1);
            raH[kk * 4 + 3] = pack_hi2(v6, v7, l0, l1); raL[kk * 4 + 3] = pack_bf2(l0, l1);
        }
        // quad-reduce s_p
        s0 += __shfl_xor_sync(0xffffffffu, s0, 1);
        s0 += __shfl_xor_sync(0xffffffffu, s0, 2);
        s1 += __shfl_xor_sync(0xffffffffu, s1, 1);
        s1 += __shfl_xor_sync(0xffffffffu, s1, 2);
        if (t == 0) { svals[p0] = s0; svals[p1] = s1; }

        // GEMM: D[16,64] = A * W1^T, 3-term bf16 split
        float acc[8][4];
        #pragma unroll
        for (int n = 0; n < 8; ++n)
            acc[n][0] = acc[n][1] = acc[n][2] = acc[n][3] = 0.f;

        #pragma unroll
        for (int n = 0; n < 8; ++n) {
            const int h = n * 8 + gid;
            #pragma unroll
            for (int kk = 0; kk < 4; ++kk) {
                const uint32_t bh0 = sW1h[h][kk * 8 + t];
                const uint32_t bh1 = sW1h[h][kk * 8 + t + 4];
                const uint32_t bl0 = sW1l[h][kk * 8 + t];
                const uint32_t bl1 = sW1l[h][kk * 8 + t + 4];
                mma16816(acc[n], raH[kk*4+0], raH[kk*4+1], raH[kk*4+2], raH[kk*4+3], bh0, bh1);
                mma16816(acc[n], raL[kk*4+0], raL[kk*4+1], raL[kk*4+2], raL[kk*4+3], bh0, bh1);
                mma16816(acc[n], raH[kk*4+0], raH[kk*4+1], raH[kk*4+2], raH[kk*4+3], bl0, bl1);
            }
        }

        // epilogue: logit = sum_h relu(D + b1[h]) * W2[h]
        float lg0 = 0.f, lg1 = 0.f;
        #pragma unroll
        for (int n = 0; n < 8; ++n) {
            const int h0 = n * 8 + 2 * t;
            const float2 bb = *(const float2*)&sb1[h0];
            const float2 ww = *(const float2*)&sW2[h0];
            lg0 = fmaf(fmaxf(acc[n][0] + bb.x, 0.f), ww.x, lg0);
            lg0 = fmaf(fmaxf(acc[n][1] + bb.y, 0.f), ww.y, lg0);
            lg1 = fmaf(fmaxf(acc[n][2] + bb.x, 0.f), ww.x, lg1);
            lg1 = fmaf(fmaxf(acc[n][3] + bb.y, 0.f), ww.y, lg1);
        }
        lg0 += __shfl_xor_sync(0xffffffffu, lg0, 1);
        lg0 += __shfl_xor_sync(0xffffffffu, lg0, 2);
        lg1 += __shfl_xor_sync(0xffffffffu, lg1, 1);
        lg1 += __shfl_xor_sync(0xffffffffu, lg1, 2);
        if (t == 0) { logits[p0] = lg0 + b2v; logits[p1] = lg1 + b2v; }
    }
    __syncthreads();

    // ---- block-wide online softmax over 780 pairs ----
    float m = -FLT_MAX, Z = 0.f, S = 0.f;
    for (int p = tid; p < NPAIR; p += NT) {
        const float l = logits[p];
        const float s = svals[p];
        const float mn = fmaxf(m, l);
        const float sc = __expf(m - mn);
        const float w  = __expf(l - mn);
        Z = Z * sc + w;
        S = S * sc + s * w;
        m = mn;
    }
    #pragma unroll
    for (int off = 16; off; off >>= 1) {
        const float m2 = __shfl_down_sync(0xffffffffu, m, off);
        const float Z2 = __shfl_down_sync(0xffffffffu, Z, off);
        const float S2 = __shfl_down_sync(0xffffffffu, S, off);
        const float mn = fmaxf(m, m2);
        const float e1 = __expf(m - mn);
        const float e2 = __expf(m2 - mn);
        Z = Z * e1 + Z2 * e2;
        S = S * e1 + S2 * e2;
        m = mn;
    }
    if (lid == 0) { red[wid] = m; red[8 + wid] = Z; red[16 + wid] = S; }
    __syncthreads();
    if (wid == 0) {
        m = (lid < 8) ? red[lid] : -FLT_MAX;
        Z = (lid < 8) ? red[8 + lid] : 0.f;
        S = (lid < 8) ? red[16 + lid] : 0.f;
        #pragma unroll
        for (int off = 4; off; off >>= 1) {
            const float m2 = __shfl_down_sync(0xffffffffu, m, off);
            const float Z2 = __shfl_down_sync(0xffffffffu, Z, off);
            const float S2 = __shfl_down_sync(0xffffffffu, S, off);
            const float mn = fmaxf(m, m2);
            const float e1 = __expf(m - mn);
            const float e2 = __expf(m2 - mn);
            Z = Z * e1 + Z2 * e2;
            S = S * e1 + S2 * e2;
            m = mn;
        }
        if (lid == 0) out[b] = S / Z + blv;
    }
}

}  // namespace

extern "C" void kernel_launch(void* const* d_in, const int* in_sizes, int n_in,
                              void* d_out, int out_size)
{
    const float* x  = (const float*)d_in[0];
    const float* W1 = (const float*)d_in[1];
    const float* b1 = (const float*)d_in[2];
    const float* W2 = (const float*)d_in[3];
    const float* b2 = (const float*)d_in[4];
    const float* Wl = (const float*)d_in[5];
    const float* bl = (const float*)d_in[6];
    float* out = (float*)d_out;

    const int batch = in_sizes[0] / (NF * ED);  // 2048
    afm_mma_kernel<<<batch, NT>>>(x, W1, b1, W2, b2, Wl, bl, out);
}

// round 4
// speedup vs baseline: 3.2513x; 1.1460x over previous
#include <cuda_runtime.h>
#include <cuda_bf16.h>
#include <cstdint>
#include <float.h>

// AFM fused kernel — mma.sync bf16 3-term split, M=32-blocked, transient accum.
//
// out[b] = bl + sum_p softmax_p(l_p) * s_p
//   inner_p = x[b,r]∘x[b,c]
//   s_p = inner_p·Wl                     (fp32, during A-fragment build)
//   l_p = W2·relu(W1·inner_p + b1)       (+b2 dropped: softmax shift-invariant)
//
// One CTA/batch, 8 warps. 800 pair-slots -> 25 rounds of 32 pairs (2 MMA
// M-blocks). Per round: A frags (hi/lo, K-permuted float4 build) for both
// blocks; loop n: load B frags once, 6 MMAs (2 blocks x 3 split terms) per kk,
// immediate partial epilogue into 4 logit regs. Block online softmax at end.

namespace {

constexpr int NF     = 40;
constexpr int ED     = 64;
constexpr int NPAIR  = NF * (NF - 1) / 2;   // 780
constexpr int NROUND = 25;                   // 25 * 32 = 800 slots
constexpr int NPAD   = NROUND * 32;
constexpr int NT     = 256;
constexpr int XS     = 72;                   // sx row stride (16B-aligned, low-conflict)

__device__ __forceinline__ uint32_t pack_hi2(float v0, float v1, float& l0, float& l1) {
    const uint32_t u0 = __float_as_uint(v0) & 0xffff0000u;
    const uint32_t u1 = __float_as_uint(v1) & 0xffff0000u;
    l0 = v0 - __uint_as_float(u0);
    l1 = v1 - __uint_as_float(u1);
    return __byte_perm(u0, u1, 0x7632);
}
__device__ __forceinline__ uint32_t pack_bf2(float l0, float l1) {
    uint32_t r;
    asm("cvt.rn.bf16x2.f32 %0, %1, %2;" : "=r"(r) : "f"(l1), "f"(l0));
    return r;
}
__device__ __forceinline__ void mma16816(float* c, const uint32_t* a,
                                         uint32_t b0, uint32_t b1) {
    asm volatile(
        "mma.sync.aligned.m16n8k16.row.col.f32.bf16.bf16.f32 "
        "{%0,%1,%2,%3}, {%4,%5,%6,%7}, {%8,%9}, {%0,%1,%2,%3};"
        : "+f"(c[0]), "+f"(c[1]), "+f"(c[2]), "+f"(c[3])
        : "r"(a[0]), "r"(a[1]), "r"(a[2]), "r"(a[3]), "r"(b0), "r"(b1));
}

__global__ __launch_bounds__(NT, 2)
void afm_mma_kernel(const float* __restrict__ x,
                    const float* __restrict__ W1,
                    const float* __restrict__ b1,
                    const float* __restrict__ W2,
                    const float* __restrict__ b2,
                    const float* __restrict__ Wl,
                    const float* __restrict__ bl,
                    float* __restrict__ out)
{
    __shared__ __align__(16) float    sx[NF * XS];
    __shared__           uint32_t sW1h[ED][36];   // K-permuted packed bf16x2
    __shared__           uint32_t sW1l[ED][36];
    __shared__ __align__(16) float    sWl[ED];
    __shared__ __align__(16) float4   sEpi[32];   // (b1,W2,b1,W2) per (n,t)
    __shared__           float    logits[NPAD];
    __shared__           float    svals[NPAD];
    __shared__           uint32_t pairs[NPAD];
    __shared__           float    red[24];
    __shared__           float    scal1[1];

    const int tid = threadIdx.x;
    const int wid = tid >> 5, lid = tid & 31;
    const int gid = lid >> 2, t = lid & 3;
    const int b = blockIdx.x;

    // ---- stage x[b] ----
    const float* xb = x + (long)b * NF * ED;
    for (int i = tid; i < NF * ED; i += NT) sx[(i >> 6) * XS + (i & 63)] = xb[i];

    // ---- stage W1 hi/lo, K-permuted packing ----
    // word w = kk*8 + q*4 + t  holds  W1[h][e0], W1[h][e0+1], e0 = kk*16+4t+2q
    for (int i = tid; i < ED * 32; i += NT) {
        const int h = i >> 5, w = i & 31;
        const int kk = w >> 3, q = (w >> 2) & 1, tt = w & 3;
        const int e0 = kk * 16 + 4 * tt + 2 * q;
        const float v0 = W1[h * 64 + e0];
        const float v1 = W1[h * 64 + e0 + 1];
        float l0, l1;
        sW1h[h][w] = pack_hi2(v0, v1, l0, l1);
        sW1l[h][w] = pack_bf2(l0, l1);
    }
    if (tid < 64) sWl[tid] = Wl[tid];
    if (tid < 32) {
        const int n = tid >> 2, tt = tid & 3;
        const int h0 = n * 8 + 2 * tt;
        sEpi[tid] = make_float4(b1[h0], W2[h0], b1[h0 + 1], W2[h0 + 1]);
    }
    if (tid == 0) scal1[0] = bl[0];

    // ---- pair index table ----
    for (int p = tid; p < NPAD; p += NT) {
        if (p < NPAIR) {
            int r = 0, rem = p;
            while (rem >= NF - 1 - r) { rem -= NF - 1 - r; ++r; }
            pairs[p] = ((uint32_t)r << 8) | (uint32_t)(r + 1 + rem);
        } else {
            pairs[p] = 1u;  // dummy (0,1)
        }
    }
    __syncthreads();

    const float blv = scal1[0];

    for (int rnd = wid; rnd < NROUND; rnd += 8) {
        const int tb = rnd * 32;

        // ---- A-build: 2 blocks of 16 pairs, frags in regs (K-permuted) ----
        uint32_t raH[2][16], raL[2][16];
        float sp[4];
        #pragma unroll
        for (int blk = 0; blk < 2; ++blk) {
            const int p0 = tb + blk * 16 + gid;
            const uint32_t rc0 = pairs[p0], rc1 = pairs[p0 + 8];
            const float* xr0 = sx + (rc0 >> 8) * XS;
            const float* xc0 = sx + (rc0 & 255u) * XS;
            const float* xr1 = sx + (rc1 >> 8) * XS;
            const float* xc1 = sx + (rc1 & 255u) * XS;
            float s0 = 0.f, s1 = 0.f;
            #pragma unroll
            for (int kk = 0; kk < 4; ++kk) {
                const int e = kk * 16 + 4 * t;
                const float4 wl = *(const float4*)&sWl[e];
                float4 a, c;
                a = *(const float4*)(xr0 + e); c = *(const float4*)(xc0 + e);
                const float v0 = a.x * c.x, v1 = a.y * c.y;
                const float v2 = a.z * c.z, v3 = a.w * c.w;
                a = *(const float4*)(xr1 + e); c = *(const float4*)(xc1 + e);
                const float v4 = a.x * c.x, v5 = a.y * c.y;
                const float v6 = a.z * c.z, v7 = a.w * c.w;

                s0 = fmaf(v0, wl.x, s0); s0 = fmaf(v1, wl.y, s0);
                s0 = fmaf(v2, wl.z, s0); s0 = fmaf(v3, wl.w, s0);
                s1 = fmaf(v4, wl.x, s1); s1 = fmaf(v5, wl.y, s1);
                s1 = fmaf(v6, wl.z, s1); s1 = fmaf(v7, wl.w, s1);

                float l0, l1;
                raH[blk][kk*4+0] = pack_hi2(v0, v1, l0, l1); raL[blk][kk*4+0] = pack_bf2(l0, l1);
                raH[blk][kk*4+1] = pack_hi2(v4, v5, l0, l1); raL[blk][kk*4+1] = pack_bf2(l0, l1);
                raH[blk][kk*4+2] = pack_hi2(v2, v3, l0, l1); raL[blk][kk*4+2] = pack_bf2(l0, l1);
                raH[blk][kk*4+3] = pack_hi2(v6, v7, l0, l1); raL[blk][kk*4+3] = pack_bf2(l0, l1);
            }
            sp[blk * 2]     = s0;
            sp[blk * 2 + 1] = s1;
        }
        #pragma unroll
        for (int j = 0; j < 4; ++j) {
            sp[j] += __shfl_xor_sync(0xffffffffu, sp[j], 1);
            sp[j] += __shfl_xor_sync(0xffffffffu, sp[j], 2);
        }
        if (t == 0) {
            svals[tb + gid]      = sp[0];
            svals[tb + gid + 8]  = sp[1];
            svals[tb + 16 + gid] = sp[2];
            svals[tb + 24 + gid] = sp[3];
        }

        // ---- GEMM + fused partial epilogue, n outer, transient acc ----
        float lg[4] = {0.f, 0.f, 0.f, 0.f};
        #pragma unroll
        for (int n = 0; n < 8; ++n) {
            const int hB = n * 8 + gid;
            const uint32_t* rowH = sW1h[hB];
            const uint32_t* rowL = sW1l[hB];
            float acc0[4] = {0.f, 0.f, 0.f, 0.f};
            float acc1[4] = {0.f, 0.f, 0.f, 0.f};
            #pragma unroll
            for (int kk = 0; kk < 4; ++kk) {
                const uint32_t bh0 = rowH[kk * 8 + t];
                const uint32_t bh1 = rowH[kk * 8 + 4 + t];
                const uint32_t bl0 = rowL[kk * 8 + t];
                const uint32_t bl1 = rowL[kk * 8 + 4 + t];
                mma16816(acc0, &raH[0][kk * 4], bh0, bh1);
                mma16816(acc0, &raL[0][kk * 4], bh0, bh1);
                mma16816(acc0, &raH[0][kk * 4], bl0, bl1);
                mma16816(acc1, &raH[1][kk * 4], bh0, bh1);
                mma16816(acc1, &raL[1][kk * 4], bh0, bh1);
                mma16816(acc1, &raH[1][kk * 4], bl0, bl1);
            }
            const float4 ep = sEpi[n * 4 + t];
            lg[0] = fmaf(fmaxf(acc0[0] + ep.x, 0.f), ep.y,
                    fmaf(fmaxf(acc0[1] + ep.z, 0.f), ep.w, lg[0]));
            lg[1] = fmaf(fmaxf(acc0[2] + ep.x, 0.f), ep.y,
                    fmaf(fmaxf(acc0[3] + ep.z, 0.f), ep.w, lg[1]));
            lg[2] = fmaf(fmaxf(acc1[0] + ep.x, 0.f), ep.y,
                    fmaf(fmaxf(acc1[1] + ep.z, 0.f), ep.w, lg[2]));
            lg[3] = fmaf(fmaxf(acc1[2] + ep.x, 0.f), ep.y,
                    fmaf(fmaxf(acc1[3] + ep.z, 0.f), ep.w, lg[3]));
        }
        #pragma unroll
        for (int j = 0; j < 4; ++j) {
            lg[j] += __shfl_xor_sync(0xffffffffu, lg[j], 1);
            lg[j] += __shfl_xor_sync(0xffffffffu, lg[j], 2);
        }
        if (t == 0) {
            logits[tb + gid]      = lg[0];
            logits[tb + gid + 8]  = lg[1];
            logits[tb + 16 + gid] = lg[2];
            logits[tb + 24 + gid] = lg[3];
        }
    }
    __syncthreads();

    // ---- block-wide online softmax over 780 pairs ----
    float m = -FLT_MAX, Z = 0.f, S = 0.f;
    for (int p = tid; p < NPAIR; p += NT) {
        const float l = logits[p];
        const float s = svals[p];
        const float mn = fmaxf(m, l);
        const float sc = __expf(m - mn);
        const float w  = __expf(l - mn);
        Z = Z * sc + w;
        S = S * sc + s * w;
        m = mn;
    }
    #pragma unroll
    for (int off = 16; off; off >>= 1) {
        const float m2 = __shfl_down_sync(0xffffffffu, m, off);
        const float Z2 = __shfl_down_sync(0xffffffffu, Z, off);
        const float S2 = __shfl_down_sync(0xffffffffu, S, off);
        const float mn = fmaxf(m, m2);
        const float e1 = __expf(m - mn);
        const float e2 = __expf(m2 - mn);
        Z = Z * e1 + Z2 * e2;
        S = S * e1 + S2 * e2;
        m = mn;
    }
    if (lid == 0) { red[wid] = m; red[8 + wid] = Z; red[16 + wid] = S; }
    __syncthreads();
    if (wid == 0) {
        m = (lid < 8) ? red[lid] : -FLT_MAX;
        Z = (lid < 8) ? red[8 + lid] : 0.f;
        S = (lid < 8) ? red[16 + lid] : 0.f;
        #pragma unroll
        for (int off = 4; off; off >>= 1) {
            const float m2 = __shfl_down_sync(0xffffffffu, m, off);
            const float Z2 = __shfl_down_sync(0xffffffffu, Z, off);
            const float S2 = __shfl_down_sync(0xffffffffu, S, off);
            const float mn = fmaxf(m, m2);
            const float e1 = __expf(m - mn);
            const float e2 = __expf(m2 - mn);
            Z = Z * e1 + Z2 * e2;
            S = S * e1 + S2 * e2;
            m = mn;
        }
        if (lid == 0) out[b] = S / Z + blv;
    }
}

}  // namespace

extern "C" void kernel_launch(void* const* d_in, const int* in_sizes, int n_in,
                              void* d_out, int out_size)
{
    const float* x  = (const float*)d_in[0];
    const float* W1 = (const float*)d_in[1];
    const float* b1 = (const float*)d_in[2];
    const float* W2 = (const float*)d_in[3];
    const float* b2 = (const float*)d_in[4];
    const float* Wl = (const float*)d_in[5];
    const float* bl = (const float*)d_in[6];
    float* out = (float*)d_out;

    const int batch = in_sizes[0] / (NF * ED);  // 2048
    afm_mma_kernel<<<batch, NT>>>(x, W1, b1, W2, b2, Wl, bl, out);
}

// round 5
// speedup vs baseline: 3.3067x; 1.0171x over previous
#include <cuda_runtime.h>
#include <cuda_bf16.h>
#include <cstdint>
#include <float.h>

// AFM fused kernel — mma.sync bf16 3-term split, 3 independent acc chains,
// 16-pair tiles, 3 CTAs/SM.
//
// out[b] = bl + sum_p softmax_p(l_p) * s_p
//   inner_p = x[b,r]∘x[b,c]
//   s_p = inner_p·Wl                     (fp32, during A-fragment build)
//   l_p = W2·relu(W1·inner_p + b1)       (+b2 dropped: softmax shift-invariant)
//
// One CTA/batch, 8 warps, 49 tiles of 16 pairs, warp-strided. Per tile:
// A frags (hi/lo, K-permuted float4 build); per n: load 4 B words, 12 MMAs
// into 3 independent 4-deep chains (AhBh / AlBh / AhBl), sum, fused partial
// epilogue. Block-wide online softmax at the end.

namespace {

constexpr int NF    = 40;
constexpr int ED    = 64;
constexpr int NPAIR = NF * (NF - 1) / 2;   // 780
constexpr int NTILE = (NPAIR + 15) / 16;   // 49
constexpr int NPAD  = NTILE * 16;          // 784
constexpr int NT    = 256;
constexpr int XS    = 72;                  // sx row stride

__device__ __forceinline__ uint32_t pack_hi2(float v0, float v1, float& l0, float& l1) {
    const uint32_t u0 = __float_as_uint(v0) & 0xffff0000u;
    const uint32_t u1 = __float_as_uint(v1) & 0xffff0000u;
    l0 = v0 - __uint_as_float(u0);
    l1 = v1 - __uint_as_float(u1);
    return __byte_perm(u0, u1, 0x7632);
}
__device__ __forceinline__ uint32_t pack_bf2(float l0, float l1) {
    uint32_t r;
    asm("cvt.rn.bf16x2.f32 %0, %1, %2;" : "=r"(r) : "f"(l1), "f"(l0));
    return r;
}
__device__ __forceinline__ void mma16816(float* c, const uint32_t* a,
                                         uint32_t b0, uint32_t b1) {
    asm volatile(
        "mma.sync.aligned.m16n8k16.row.col.f32.bf16.bf16.f32 "
        "{%0,%1,%2,%3}, {%4,%5,%6,%7}, {%8,%9}, {%0,%1,%2,%3};"
        : "+f"(c[0]), "+f"(c[1]), "+f"(c[2]), "+f"(c[3])
        : "r"(a[0]), "r"(a[1]), "r"(a[2]), "r"(a[3]), "r"(b0), "r"(b1));
}

__global__ __launch_bounds__(NT, 3)
void afm_mma_kernel(const float* __restrict__ x,
                    const float* __restrict__ W1,
                    const float* __restrict__ b1,
                    const float* __restrict__ W2,
                    const float* __restrict__ b2,
                    const float* __restrict__ Wl,
                    const float* __restrict__ bl,
                    float* __restrict__ out)
{
    __shared__ __align__(16) float    sx[NF * XS];
    __shared__           uint32_t sW1h[ED][36];   // K-permuted packed bf16x2
    __shared__           uint32_t sW1l[ED][36];
    __shared__ __align__(16) float    sWl[ED];
    __shared__ __align__(16) float4   sEpi[32];   // (b1,W2,b1,W2) per (n,t)
    __shared__           float    logits[NPAD];
    __shared__           float    svals[NPAD];
    __shared__           uint32_t pairs[NPAD];
    __shared__           float    red[24];
    __shared__           float    scal1[1];

    const int tid = threadIdx.x;
    const int wid = tid >> 5, lid = tid & 31;
    const int gid = lid >> 2, t = lid & 3;
    const int b = blockIdx.x;

    // ---- stage x[b] ----
    const float* xb = x + (long)b * NF * ED;
    for (int i = tid; i < NF * ED; i += NT) sx[(i >> 6) * XS + (i & 63)] = xb[i];

    // ---- stage W1 hi/lo, K-permuted packing ----
    // word w = kk*8 + q*4 + t holds W1[h][e0..e0+1], e0 = kk*16 + 4t + 2q
    for (int i = tid; i < ED * 32; i += NT) {
        const int h = i >> 5, w = i & 31;
        const int kk = w >> 3, q = (w >> 2) & 1, tt = w & 3;
        const int e0 = kk * 16 + 4 * tt + 2 * q;
        const float v0 = W1[h * 64 + e0];
        const float v1 = W1[h * 64 + e0 + 1];
        float l0, l1;
        sW1h[h][w] = pack_hi2(v0, v1, l0, l1);
        sW1l[h][w] = pack_bf2(l0, l1);
    }
    if (tid < 64) sWl[tid] = Wl[tid];
    if (tid < 32) {
        const int n = tid >> 2, tt = tid & 3;
        const int h0 = n * 8 + 2 * tt;
        sEpi[tid] = make_float4(b1[h0], W2[h0], b1[h0 + 1], W2[h0 + 1]);
    }
    if (tid == 0) scal1[0] = bl[0];

    // ---- pair index table ----
    for (int p = tid; p < NPAD; p += NT) {
        if (p < NPAIR) {
            int r = 0, rem = p;
            while (rem >= NF - 1 - r) { rem -= NF - 1 - r; ++r; }
            pairs[p] = ((uint32_t)r << 8) | (uint32_t)(r + 1 + rem);
        } else {
            pairs[p] = 1u;  // dummy (0,1)
        }
    }
    __syncthreads();

    const float blv = scal1[0];

    for (int tile = wid; tile < NTILE; tile += 8) {
        const int tb = tile * 16;
        const int p0 = tb + gid;

        // ---- A-build: 16 pairs, frags in regs (K-permuted) + s_p partials ----
        const uint32_t rc0 = pairs[p0], rc1 = pairs[p0 + 8];
        const float* xr0 = sx + (rc0 >> 8) * XS;
        const float* xc0 = sx + (rc0 & 255u) * XS;
        const float* xr1 = sx + (rc1 >> 8) * XS;
        const float* xc1 = sx + (rc1 & 255u) * XS;

        uint32_t raH[16], raL[16];
        float s0 = 0.f, s1 = 0.f;
        #pragma unroll
        for (int kk = 0; kk < 4; ++kk) {
            const int e = kk * 16 + 4 * t;
            const float4 wl = *(const float4*)&sWl[e];
            float4 a, c;
            a = *(const float4*)(xr0 + e); c = *(const float4*)(xc0 + e);
            const float v0 = a.x * c.x, v1 = a.y * c.y;
            const float v2 = a.z * c.z, v3 = a.w * c.w;
            a = *(const float4*)(xr1 + e); c = *(const float4*)(xc1 + e);
            const float v4 = a.x * c.x, v5 = a.y * c.y;
            const float v6 = a.z * c.z, v7 = a.w * c.w;

            s0 = fmaf(v0, wl.x, s0); s0 = fmaf(v1, wl.y, s0);
            s0 = fmaf(v2, wl.z, s0); s0 = fmaf(v3, wl.w, s0);
            s1 = fmaf(v4, wl.x, s1); s1 = fmaf(v5, wl.y, s1);
            s1 = fmaf(v6, wl.z, s1); s1 = fmaf(v7, wl.w, s1);

            float l0, l1;
            raH[kk*4+0] = pack_hi2(v0, v1, l0, l1); raL[kk*4+0] = pack_bf2(l0, l1);
            raH[kk*4+1] = pack_hi2(v4, v5, l0, l1); raL[kk*4+1] = pack_bf2(l0, l1);
            raH[kk*4+2] = pack_hi2(v2, v3, l0, l1); raL[kk*4+2] = pack_bf2(l0, l1);
            raH[kk*4+3] = pack_hi2(v6, v7, l0, l1); raL[kk*4+3] = pack_bf2(l0, l1);
        }
        s0 += __shfl_xor_sync(0xffffffffu, s0, 1);
        s0 += __shfl_xor_sync(0xffffffffu, s0, 2);
        s1 += __shfl_xor_sync(0xffffffffu, s1, 1);
        s1 += __shfl_xor_sync(0xffffffffu, s1, 2);
        if (t == 0) { svals[p0] = s0; svals[p0 + 8] = s1; }

        // ---- GEMM: per n, 3 independent 4-deep chains + fused epilogue ----
        float lg0 = 0.f, lg1 = 0.f;
        #pragma unroll
        for (int n = 0; n < 8; ++n) {
            const uint32_t* rowH = sW1h[n * 8 + gid];
            const uint32_t* rowL = sW1l[n * 8 + gid];
            float aH[4] = {0.f, 0.f, 0.f, 0.f};
            float aM[4] = {0.f, 0.f, 0.f, 0.f};
            float aL[4] = {0.f, 0.f, 0.f, 0.f};
            #pragma unroll
            for (int kk = 0; kk < 4; ++kk) {
                const uint32_t bh0 = rowH[kk * 8 + t];
                const uint32_t bh1 = rowH[kk * 8 + 4 + t];
                const uint32_t bl0 = rowL[kk * 8 + t];
                const uint32_t bl1 = rowL[kk * 8 + 4 + t];
                mma16816(aH, &raH[kk * 4], bh0, bh1);
                mma16816(aM, &raL[kk * 4], bh0, bh1);
                mma16816(aL, &raH[kk * 4], bl0, bl1);
            }
            const float4 ep = sEpi[n * 4 + t];
            const float d0 = aH[0] + aM[0] + aL[0];
            const float d1 = aH[1] + aM[1] + aL[1];
            const float d2 = aH[2] + aM[2] + aL[2];
            const float d3 = aH[3] + aM[3] + aL[3];
            lg0 = fmaf(fmaxf(d0 + ep.x, 0.f), ep.y,
                  fmaf(fmaxf(d1 + ep.z, 0.f), ep.w, lg0));
            lg1 = fmaf(fmaxf(d2 + ep.x, 0.f), ep.y,
                  fmaf(fmaxf(d3 + ep.z, 0.f), ep.w, lg1));
        }
        lg0 += __shfl_xor_sync(0xffffffffu, lg0, 1);
        lg0 += __shfl_xor_sync(0xffffffffu, lg0, 2);
        lg1 += __shfl_xor_sync(0xffffffffu, lg1, 1);
        lg1 += __shfl_xor_sync(0xffffffffu, lg1, 2);
        if (t == 0) { logits[p0] = lg0; logits[p0 + 8] = lg1; }
    }
    __syncthreads();

    // ---- block-wide online softmax over 780 pairs ----
    float m = -FLT_MAX, Z = 0.f, S = 0.f;
    for (int p = tid; p < NPAIR; p += NT) {
        const float l = logits[p];
        const float s = svals[p];
        const float mn = fmaxf(m, l);
        const float sc = __expf(m - mn);
        const float w  = __expf(l - mn);
        Z = Z * sc + w;
        S = S * sc + s * w;
        m = mn;
    }
    #pragma unroll
    for (int off = 16; off; off >>= 1) {
        const float m2 = __shfl_down_sync(0xffffffffu, m, off);
        const float Z2 = __shfl_down_sync(0xffffffffu, Z, off);
        const float S2 = __shfl_down_sync(0xffffffffu, S, off);
        const float mn = fmaxf(m, m2);
        const float e1 = __expf(m - mn);
        const float e2 = __expf(m2 - mn);
        Z = Z * e1 + Z2 * e2;
        S = S * e1 + S2 * e2;
        m = mn;
    }
    if (lid == 0) { red[wid] = m; red[8 + wid] = Z; red[16 + wid] = S; }
    __syncthreads();
    if (wid == 0) {
        m = (lid < 8) ? red[lid] : -FLT_MAX;
        Z = (lid < 8) ? red[8 + lid] : 0.f;
        S = (lid < 8) ? red[16 + lid] : 0.f;
        #pragma unroll
        for (int off = 4; off; off >>= 1) {
            const float m2 = __shfl_down_sync(0xffffffffu, m, off);
            const float Z2 = __shfl_down_sync(0xffffffffu, Z, off);
            const float S2 = __shfl_down_sync(0xffffffffu, S, off);
            const float mn = fmaxf(m, m2);
            const float e1 = __expf(m - mn);
            const float e2 = __expf(m2 - mn);
            Z = Z * e1 + Z2 * e2;
            S = S * e1 + S2 * e2;
            m = mn;
        }
        if (lid == 0) out[b] = S / Z + blv;
    }
}

}  // namespace

extern "C" void kernel_launch(void* const* d_in, const int* in_sizes, int n_in,
                              void* d_out, int out_size)
{
    const float* x  = (const float*)d_in[0];
    const float* W1 = (const float*)d_in[1];
    const float* b1 = (const float*)d_in[2];
    const float* W2 = (const float*)d_in[3];
    const float* b2 = (const float*)d_in[4];
    const float* Wl = (const float*)d_in[5];
    const float* bl = (const float*)d_in[6];
    float* out = (float*)d_out;

    const int batch = in_sizes[0] / (NF * ED);  // 2048
    afm_mma_kernel<<<batch, NT>>>(x, W1, b1, W2, b2, Wl, bl, out);
}

// round 6
// speedup vs baseline: 4.1405x; 1.2521x over previous
#include <cuda_runtime.h>
#include <cuda_fp16.h>
#include <cstdint>
#include <float.h>

// AFM fused kernel — mma.sync fp16 2-term split (A = Ah+Al, B rounded),
// 16-pair tiles, 3 CTAs/SM.
//
// out[b] = bl + sum_p softmax_p(l_p) * s_p
//   inner_p = x[b,r]∘x[b,c]
//   s_p = inner_p·Wl                     (fp32, during A-fragment build)
//   l_p = W2·relu(W1·inner_p + b1)       (+b2 dropped: softmax shift-invariant)
//
// GEMM precision: D = Ah*Bh + Al*Bh with fp16 Ah=rn(A), Al=rn(A-Ah), Bh=rn(B).
// Missing term A*Bl ~ 2^-12 relative -> end-to-end ~1e-4, well under 1e-3.
//
// One CTA/batch, 8 warps, 49 tiles of 16 pairs, warp-strided. Per tile:
// A frags (hi/lo fp16, K-permuted float4 build); per n: 2 B words, 8 MMAs in
// 2 independent 4-deep chains, fused partial epilogue. Block softmax at end.

namespace {

constexpr int NF    = 40;
constexpr int ED    = 64;
constexpr int NPAIR = NF * (NF - 1) / 2;   // 780
constexpr int NTILE = (NPAIR + 15) / 16;   // 49
constexpr int NPAD  = NTILE * 16;          // 784
constexpr int NT    = 256;
constexpr int XS    = 72;                  // sx row stride

__device__ __forceinline__ uint32_t pack_h2(float v0, float v1) {
    const __half2 h = __floats2half2_rn(v0, v1);   // .x = v0 (low half)
    return *(const uint32_t*)&h;
}
// hi = fp16 rounding of (v0,v1); residuals out by reference.
__device__ __forceinline__ uint32_t pack_hi2(float v0, float v1, float& l0, float& l1) {
    const __half2 h = __floats2half2_rn(v0, v1);
    const float2 bk = __half22float2(h);
    l0 = v0 - bk.x;
    l1 = v1 - bk.y;
    return *(const uint32_t*)&h;
}
__device__ __forceinline__ void mma16816(float* c, const uint32_t* a,
                                         uint32_t b0, uint32_t b1) {
    asm volatile(
        "mma.sync.aligned.m16n8k16.row.col.f32.f16.f16.f32 "
        "{%0,%1,%2,%3}, {%4,%5,%6,%7}, {%8,%9}, {%0,%1,%2,%3};"
        : "+f"(c[0]), "+f"(c[1]), "+f"(c[2]), "+f"(c[3])
        : "r"(a[0]), "r"(a[1]), "r"(a[2]), "r"(a[3]), "r"(b0), "r"(b1));
}

__global__ __launch_bounds__(NT, 3)
void afm_mma_kernel(const float* __restrict__ x,
                    const float* __restrict__ W1,
                    const float* __restrict__ b1,
                    const float* __restrict__ W2,
                    const float* __restrict__ b2,
                    const float* __restrict__ Wl,
                    const float* __restrict__ bl,
                    float* __restrict__ out)
{
    __shared__ __align__(16) float    sx[NF * XS];
    __shared__           uint32_t sW1h[ED][36];   // K-permuted packed fp16x2
    __shared__ __align__(16) float    sWl[ED];
    __shared__ __align__(16) float4   sEpi[32];   // (b1,W2,b1,W2) per (n,t)
    __shared__           float    logits[NPAD];
    __shared__           float    svals[NPAD];
    __shared__           uint32_t pairs[NPAD];
    __shared__           float    red[24];
    __shared__           float    scal1[1];

    const int tid = threadIdx.x;
    const int wid = tid >> 5, lid = tid & 31;
    const int gid = lid >> 2, t = lid & 3;
    const int b = blockIdx.x;

    // ---- stage x[b] ----
    const float* xb = x + (long)b * NF * ED;
    for (int i = tid; i < NF * ED; i += NT) sx[(i >> 6) * XS + (i & 63)] = xb[i];

    // ---- stage W1 (fp16 rounded), K-permuted packing ----
    // word w = kk*8 + q*4 + t holds W1[h][e0..e0+1], e0 = kk*16 + 4t + 2q
    for (int i = tid; i < ED * 32; i += NT) {
        const int h = i >> 5, w = i & 31;
        const int kk = w >> 3, q = (w >> 2) & 1, tt = w & 3;
        const int e0 = kk * 16 + 4 * tt + 2 * q;
        sW1h[h][w] = pack_h2(W1[h * 64 + e0], W1[h * 64 + e0 + 1]);
    }
    if (tid < 64) sWl[tid] = Wl[tid];
    if (tid < 32) {
        const int n = tid >> 2, tt = tid & 3;
        const int h0 = n * 8 + 2 * tt;
        sEpi[tid] = make_float4(b1[h0], W2[h0], b1[h0 + 1], W2[h0 + 1]);
    }
    if (tid == 0) scal1[0] = bl[0];

    // ---- pair index table ----
    for (int p = tid; p < NPAD; p += NT) {
        if (p < NPAIR) {
            int r = 0, rem = p;
            while (rem >= NF - 1 - r) { rem -= NF - 1 - r; ++r; }
            pairs[p] = ((uint32_t)r << 8) | (uint32_t)(r + 1 + rem);
        } else {
            pairs[p] = 1u;  // dummy (0,1)
        }
    }
    __syncthreads();

    const float blv = scal1[0];

    for (int tile = wid; tile < NTILE; tile += 8) {
        const int tb = tile * 16;
        const int p0 = tb + gid;

        // ---- A-build: 16 pairs, fp16 hi/lo frags (K-permuted) + s_p ----
        const uint32_t rc0 = pairs[p0], rc1 = pairs[p0 + 8];
        const float* xr0 = sx + (rc0 >> 8) * XS;
        const float* xc0 = sx + (rc0 & 255u) * XS;
        const float* xr1 = sx + (rc1 >> 8) * XS;
        const float* xc1 = sx + (rc1 & 255u) * XS;

        uint32_t raH[16], raL[16];
        float s0 = 0.f, s1 = 0.f;
        #pragma unroll
        for (int kk = 0; kk < 4; ++kk) {
            const int e = kk * 16 + 4 * t;
            const float4 wl = *(const float4*)&sWl[e];
            float4 a, c;
            a = *(const float4*)(xr0 + e); c = *(const float4*)(xc0 + e);
            const float v0 = a.x * c.x, v1 = a.y * c.y;
            const float v2 = a.z * c.z, v3 = a.w * c.w;
            a = *(const float4*)(xr1 + e); c = *(const float4*)(xc1 + e);
            const float v4 = a.x * c.x, v5 = a.y * c.y;
            const float v6 = a.z * c.z, v7 = a.w * c.w;

            s0 = fmaf(v0, wl.x, s0); s0 = fmaf(v1, wl.y, s0);
            s0 = fmaf(v2, wl.z, s0); s0 = fmaf(v3, wl.w, s0);
            s1 = fmaf(v4, wl.x, s1); s1 = fmaf(v5, wl.y, s1);
            s1 = fmaf(v6, wl.z, s1); s1 = fmaf(v7, wl.w, s1);

            float l0, l1;
            raH[kk*4+0] = pack_hi2(v0, v1, l0, l1); raL[kk*4+0] = pack_h2(l0, l1);
            raH[kk*4+1] = pack_hi2(v4, v5, l0, l1); raL[kk*4+1] = pack_h2(l0, l1);
            raH[kk*4+2] = pack_hi2(v2, v3, l0, l1); raL[kk*4+2] = pack_h2(l0, l1);
            raH[kk*4+3] = pack_hi2(v6, v7, l0, l1); raL[kk*4+3] = pack_h2(l0, l1);
        }
        s0 += __shfl_xor_sync(0xffffffffu, s0, 1);
        s0 += __shfl_xor_sync(0xffffffffu, s0, 2);
        s1 += __shfl_xor_sync(0xffffffffu, s1, 1);
        s1 += __shfl_xor_sync(0xffffffffu, s1, 2);
        if (t == 0) { svals[p0] = s0; svals[p0 + 8] = s1; }

        // ---- GEMM: per n, 2 independent 4-deep chains + fused epilogue ----
        float lg0 = 0.f, lg1 = 0.f;
        #pragma unroll
        for (int n = 0; n < 8; ++n) {
            const uint32_t* rowH = sW1h[n * 8 + gid];
            float aH[4] = {0.f, 0.f, 0.f, 0.f};
            float aL[4] = {0.f, 0.f, 0.f, 0.f};
            #pragma unroll
            for (int kk = 0; kk < 4; ++kk) {
                const uint32_t bh0 = rowH[kk * 8 + t];
                const uint32_t bh1 = rowH[kk * 8 + 4 + t];
                mma16816(aH, &raH[kk * 4], bh0, bh1);
                mma16816(aL, &raL[kk * 4], bh0, bh1);
            }
            const float4 ep = sEpi[n * 4 + t];
            const float d0 = aH[0] + aL[0];
            const float d1 = aH[1] + aL[1];
            const float d2 = aH[2] + aL[2];
            const float d3 = aH[3] + aL[3];
            lg0 = fmaf(fmaxf(d0 + ep.x, 0.f), ep.y,
                  fmaf(fmaxf(d1 + ep.z, 0.f), ep.w, lg0));
            lg1 = fmaf(fmaxf(d2 + ep.x, 0.f), ep.y,
                  fmaf(fmaxf(d3 + ep.z, 0.f), ep.w, lg1));
        }
        lg0 += __shfl_xor_sync(0xffffffffu, lg0, 1);
        lg0 += __shfl_xor_sync(0xffffffffu, lg0, 2);
        lg1 += __shfl_xor_sync(0xffffffffu, lg1, 1);
        lg1 += __shfl_xor_sync(0xffffffffu, lg1, 2);
        if (t == 0) { logits[p0] = lg0; logits[p0 + 8] = lg1; }
    }
    __syncthreads();

    // ---- block-wide online softmax over 780 pairs ----
    float m = -FLT_MAX, Z = 0.f, S = 0.f;
    for (int p = tid; p < NPAIR; p += NT) {
        const float l = logits[p];
        const float s = svals[p];
        const float mn = fmaxf(m, l);
        const float sc = __expf(m - mn);
        const float w  = __expf(l - mn);
        Z = Z * sc + w;
        S = S * sc + s * w;
        m = mn;
    }
    #pragma unroll
    for (int off = 16; off; off >>= 1) {
        const float m2 = __shfl_down_sync(0xffffffffu, m, off);
        const float Z2 = __shfl_down_sync(0xffffffffu, Z, off);
        const float S2 = __shfl_down_sync(0xffffffffu, S, off);
        const float mn = fmaxf(m, m2);
        const float e1 = __expf(m - mn);
        const float e2 = __expf(m2 - mn);
        Z = Z * e1 + Z2 * e2;
        S = S * e1 + S2 * e2;
        m = mn;
    }
    if (lid == 0) { red[wid] = m; red[8 + wid] = Z; red[16 + wid] = S; }
    __syncthreads();
    if (wid == 0) {
        m = (lid < 8) ? red[lid] : -FLT_MAX;
        Z = (lid < 8) ? red[8 + lid] : 0.f;
        S = (lid < 8) ? red[16 + lid] : 0.f;
        #pragma unroll
        for (int off = 4; off; off >>= 1) {
            const float m2 = __shfl_down_sync(0xffffffffu, m, off);
            const float Z2 = __shfl_down_sync(0xffffffffu, Z, off);
            const float S2 = __shfl_down_sync(0xffffffffu, S, off);
            const float mn = fmaxf(m, m2);
            const float e1 = __expf(m - mn);
            const float e2 = __expf(m2 - mn);
            Z = Z * e1 + Z2 * e2;
            S = S * e1 + S2 * e2;
            m = mn;
        }
        if (lid == 0) out[b] = S / Z + blv;
    }
}

}  // namespace

extern "C" void kernel_launch(void* const* d_in, const int* in_sizes, int n_in,
                              void* d_out, int out_size)
{
    const float* x  = (const float*)d_in[0];
    const float* W1 = (const float*)d_in[1];
    const float* b1 = (const float*)d_in[2];
    const float* W2 = (const float*)d_in[3];
    const float* b2 = (const float*)d_in[4];
    const float* Wl = (const float*)d_in[5];
    const float* bl = (const float*)d_in[6];
    float* out = (float*)d_out;

    const int batch = in_sizes[0] / (NF * ED);  // 2048
    afm_mma_kernel<<<batch, NT>>>(x, W1, b1, W2, b2, Wl, bl, out);
}

// round 7
// speedup vs baseline: 4.3253x; 1.0446x over previous
#include <cuda_runtime.h>
#include <cuda_fp16.h>
#include <cstdint>
#include <float.h>

// AFM fused kernel — mma.sync fp16 2-term split, W1 fully register-resident.
//
// out[b] = bl + sum_p softmax_p(l_p) * s_p
//   inner_p = x[b,r]∘x[b,c]
//   s_p = inner_p·Wl                     (fp32, during A-fragment build)
//   l_p = W2·relu(W1·inner_p + b1)       (+b2 dropped: softmax shift-invariant)
//
// GEMM precision: D = Ah*Bh + Al*Bh, fp16 Ah=rn(A), Al=rn(A-Ah), Bh=rn(B).
//
// W1 (64x64 fp16 = 8KB = 64 regs/thread warp-wide) lives ENTIRELY in
// registers, loaded once — zero B smem traffic in the main loop.
// Loop order: tile -> kk(outer, A frags transient) -> n(8 persistent acc
// chains, depth-2 per kk). Fused epilogue per tile; block softmax at end.

namespace {

constexpr int NF    = 40;
constexpr int ED    = 64;
constexpr int NPAIR = NF * (NF - 1) / 2;   // 780
constexpr int NTILE = (NPAIR + 15) / 16;   // 49
constexpr int NPAD  = NTILE * 16;          // 784
constexpr int NT    = 256;
constexpr int XS    = 72;                  // sx row stride

__device__ __forceinline__ uint32_t pack_h2(float v0, float v1) {
    const __half2 h = __floats2half2_rn(v0, v1);   // .x = v0 (low half)
    return *(const uint32_t*)&h;
}
__device__ __forceinline__ uint32_t pack_hi2(float v0, float v1, float& l0, float& l1) {
    const __half2 h = __floats2half2_rn(v0, v1);
    const float2 bk = __half22float2(h);
    l0 = v0 - bk.x;
    l1 = v1 - bk.y;
    return *(const uint32_t*)&h;
}
__device__ __forceinline__ void mma16816(float* c, const uint32_t* a,
                                         uint32_t b0, uint32_t b1) {
    asm volatile(
        "mma.sync.aligned.m16n8k16.row.col.f32.f16.f16.f32 "
        "{%0,%1,%2,%3}, {%4,%5,%6,%7}, {%8,%9}, {%0,%1,%2,%3};"
        : "+f"(c[0]), "+f"(c[1]), "+f"(c[2]), "+f"(c[3])
        : "r"(a[0]), "r"(a[1]), "r"(a[2]), "r"(a[3]), "r"(b0), "r"(b1));
}

__global__ __launch_bounds__(NT, 2)
void afm_mma_kernel(const float* __restrict__ x,
                    const float* __restrict__ W1,
                    const float* __restrict__ b1,
                    const float* __restrict__ W2,
                    const float* __restrict__ b2,
                    const float* __restrict__ Wl,
                    const float* __restrict__ bl,
                    float* __restrict__ out)
{
    __shared__ __align__(16) float    sx[NF * XS];
    __shared__           uint32_t sW1h[ED][36];   // staging for B frag load
    __shared__ __align__(16) float    sWl[ED];
    __shared__ __align__(16) float4   sEpi[32];   // (b1,W2,b1,W2) per (n,t)
    __shared__           float    logits[NPAD];
    __shared__           float    svals[NPAD];
    __shared__           uint32_t pairs[NPAD];
    __shared__           float    red[24];
    __shared__           float    scal1[1];

    const int tid = threadIdx.x;
    const int wid = tid >> 5, lid = tid & 31;
    const int gid = lid >> 2, t = lid & 3;
    const int b = blockIdx.x;

    // ---- stage x[b] ----
    const float* xb = x + (long)b * NF * ED;
    for (int i = tid; i < NF * ED; i += NT) sx[(i >> 6) * XS + (i & 63)] = xb[i];

    // ---- stage W1 (fp16 rounded), K-permuted packing ----
    // word w = kk*8 + q*4 + t holds W1[h][e0..e0+1], e0 = kk*16 + 4t + 2q
    for (int i = tid; i < ED * 32; i += NT) {
        const int h = i >> 5, w = i & 31;
        const int kk = w >> 3, q = (w >> 2) & 1, tt = w & 3;
        const int e0 = kk * 16 + 4 * tt + 2 * q;
        sW1h[h][w] = pack_h2(W1[h * 64 + e0], W1[h * 64 + e0 + 1]);
    }
    if (tid < 64) sWl[tid] = Wl[tid];
    if (tid < 32) {
        const int n = tid >> 2, tt = tid & 3;
        const int h0 = n * 8 + 2 * tt;
        sEpi[tid] = make_float4(b1[h0], W2[h0], b1[h0 + 1], W2[h0 + 1]);
    }
    if (tid == 0) scal1[0] = bl[0];

    // ---- pair index table ----
    for (int p = tid; p < NPAD; p += NT) {
        if (p < NPAIR) {
            int r = 0, rem = p;
            while (rem >= NF - 1 - r) { rem -= NF - 1 - r; ++r; }
            pairs[p] = ((uint32_t)r << 8) | (uint32_t)(r + 1 + rem);
        } else {
            pairs[p] = 1u;  // dummy (0,1)
        }
    }
    __syncthreads();

    const float blv = scal1[0];

    // ---- load ALL B fragments into registers (whole W1, warp-wide) ----
    // bf[n][kk][w] : w=0 -> word kk*8+t, w=1 -> word kk*8+4+t, row n*8+gid
    uint32_t bf[8][4][2];
    #pragma unroll
    for (int n = 0; n < 8; ++n) {
        const uint32_t* rowH = sW1h[n * 8 + gid];
        #pragma unroll
        for (int kk = 0; kk < 4; ++kk) {
            bf[n][kk][0] = rowH[kk * 8 + t];
            bf[n][kk][1] = rowH[kk * 8 + 4 + t];
        }
    }

    for (int tile = wid; tile < NTILE; tile += 8) {
        const int p0 = tile * 16 + gid;

        const uint32_t rc0 = pairs[p0], rc1 = pairs[p0 + 8];
        const float* xr0 = sx + (rc0 >> 8) * XS;
        const float* xc0 = sx + (rc0 & 255u) * XS;
        const float* xr1 = sx + (rc1 >> 8) * XS;
        const float* xc1 = sx + (rc1 & 255u) * XS;

        float acc[8][4];
        #pragma unroll
        for (int n = 0; n < 8; ++n)
            acc[n][0] = acc[n][1] = acc[n][2] = acc[n][3] = 0.f;

        float s0 = 0.f, s1 = 0.f;
        #pragma unroll
        for (int kk = 0; kk < 4; ++kk) {
            // ---- A frags for this kk (transient) + s_p partials ----
            const int e = kk * 16 + 4 * t;
            const float4 wl = *(const float4*)&sWl[e];
            float4 a, c;
            a = *(const float4*)(xr0 + e); c = *(const float4*)(xc0 + e);
            const float v0 = a.x * c.x, v1 = a.y * c.y;
            const float v2 = a.z * c.z, v3 = a.w * c.w;
            a = *(const float4*)(xr1 + e); c = *(const float4*)(xc1 + e);
            const float v4 = a.x * c.x, v5 = a.y * c.y;
            const float v6 = a.z * c.z, v7 = a.w * c.w;

            s0 = fmaf(v0, wl.x, s0); s0 = fmaf(v1, wl.y, s0);
            s0 = fmaf(v2, wl.z, s0); s0 = fmaf(v3, wl.w, s0);
            s1 = fmaf(v4, wl.x, s1); s1 = fmaf(v5, wl.y, s1);
            s1 = fmaf(v6, wl.z, s1); s1 = fmaf(v7, wl.w, s1);

            uint32_t raH[4], raL[4];
            float l0, l1;
            raH[0] = pack_hi2(v0, v1, l0, l1); raL[0] = pack_h2(l0, l1);
            raH[1] = pack_hi2(v4, v5, l0, l1); raL[1] = pack_h2(l0, l1);
            raH[2] = pack_hi2(v2, v3, l0, l1); raL[2] = pack_h2(l0, l1);
            raH[3] = pack_hi2(v6, v7, l0, l1); raL[3] = pack_h2(l0, l1);

            // ---- 16 MMAs into 8 independent acc chains ----
            #pragma unroll
            for (int n = 0; n < 8; ++n) {
                mma16816(acc[n], raH, bf[n][kk][0], bf[n][kk][1]);
                mma16816(acc[n], raL, bf[n][kk][0], bf[n][kk][1]);
            }
        }

        // quad-reduce s_p
        s0 += __shfl_xor_sync(0xffffffffu, s0, 1);
        s0 += __shfl_xor_sync(0xffffffffu, s0, 2);
        s1 += __shfl_xor_sync(0xffffffffu, s1, 1);
        s1 += __shfl_xor_sync(0xffffffffu, s1, 2);
        if (t == 0) { svals[p0] = s0; svals[p0 + 8] = s1; }

        // ---- fused epilogue ----
        float lg0 = 0.f, lg1 = 0.f;
        #pragma unroll
        for (int n = 0; n < 8; ++n) {
            const float4 ep = sEpi[n * 4 + t];
            lg0 = fmaf(fmaxf(acc[n][0] + ep.x, 0.f), ep.y,
                  fmaf(fmaxf(acc[n][1] + ep.z, 0.f), ep.w, lg0));
            lg1 = fmaf(fmaxf(acc[n][2] + ep.x, 0.f), ep.y,
                  fmaf(fmaxf(acc[n][3] + ep.z, 0.f), ep.w, lg1));
        }
        lg0 += __shfl_xor_sync(0xffffffffu, lg0, 1);
        lg0 += __shfl_xor_sync(0xffffffffu, lg0, 2);
        lg1 += __shfl_xor_sync(0xffffffffu, lg1, 1);
        lg1 += __shfl_xor_sync(0xffffffffu, lg1, 2);
        if (t == 0) { logits[p0] = lg0; logits[p0 + 8] = lg1; }
    }
    __syncthreads();

    // ---- block-wide online softmax over 780 pairs ----
    float m = -FLT_MAX, Z = 0.f, S = 0.f;
    for (int p = tid; p < NPAIR; p += NT) {
        const float l = logits[p];
        const float s = svals[p];
        const float mn = fmaxf(m, l);
        const float sc = __expf(m - mn);
        const float w  = __expf(l - mn);
        Z = Z * sc + w;
        S = S * sc + s * w;
        m = mn;
    }
    #pragma unroll
    for (int off = 16; off; off >>= 1) {
        const float m2 = __shfl_down_sync(0xffffffffu, m, off);
        const float Z2 = __shfl_down_sync(0xffffffffu, Z, off);
        const float S2 = __shfl_down_sync(0xffffffffu, S, off);
        const float mn = fmaxf(m, m2);
        const float e1 = __expf(m - mn);
        const float e2 = __expf(m2 - mn);
        Z = Z * e1 + Z2 * e2;
        S = S * e1 + S2 * e2;
        m = mn;
    }
    if (lid == 0) { red[wid] = m; red[8 + wid] = Z; red[16 + wid] = S; }
    __syncthreads();
    if (wid == 0) {
        m = (lid < 8) ? red[lid] : -FLT_MAX;
        Z = (lid < 8) ? red[8 + lid] : 0.f;
        S = (lid < 8) ? red[16 + lid] : 0.f;
        #pragma unroll
        for (int off = 4; off; off >>= 1) {
            const float m2 = __shfl_down_sync(0xffffffffu, m, off);
            const float Z2 = __shfl_down_sync(0xffffffffu, Z, off);
            const float S2 = __shfl_down_sync(0xffffffffu, S, off);
            const float mn = fmaxf(m, m2);
            const float e1 = __expf(m - mn);
            const float e2 = __expf(m2 - mn);
            Z = Z * e1 + Z2 * e2;
            S = S * e1 + S2 * e2;
            m = mn;
        }
        if (lid == 0) out[b] = S / Z + blv;
    }
}

}  // namespace

extern "C" void kernel_launch(void* const* d_in, const int* in_sizes, int n_in,
                              void* d_out, int out_size)
{
    const float* x  = (const float*)d_in[0];
    const float* W1 = (const float*)d_in[1];
    const float* b1 = (const float*)d_in[2];
    const float* W2 = (const float*)d_in[3];
    const float* b2 = (const float*)d_in[4];
    const float* Wl = (const float*)d_in[5];
    const float* bl = (const float*)d_in[6];
    float* out = (float*)d_out;

    const int batch = in_sizes[0] / (NF * ED);  // 2048
    afm_mma_kernel<<<batch, NT>>>(x, W1, b1, W2, b2, Wl, bl, out);
}

// round 8
// speedup vs baseline: 4.5407x; 1.0498x over previous
#include <cuda_runtime.h>
#include <cuda_fp16.h>
#include <cstdint>
#include <float.h>

// AFM fused kernel — mma.sync fp16 single-term (A,B both rn-rounded),
// W1 fully register-resident.
//
// out[b] = bl + sum_p softmax_p(l_p) * s_p
//   inner_p = x[b,r]∘x[b,c]
//   s_p = inner_p·Wl                     (fp32, during A-fragment build)
//   l_p = W2·relu(W1·inner_p + b1)       (+b2 dropped: softmax shift-invariant)
//
// GEMM precision: D = rn16(A)·rn16(B), fp32 accumulate. Measured 2-term
// (exact-A) error was 1.8e-5 = pure B-rounding; adding A-rounding of equal
// magnitude lands ~3e-5 — 25x under the 1e-3 gate.
//
// W1 (64x64 fp16 = 64 regs/thread warp-wide) entirely in registers.
// Per 16-pair tile: kk-outer A-frag build (fp32 gather, fp16 pack),
// 8 MMAs/kk into 8 independent acc chains; fused epilogue; block softmax.

namespace {

constexpr int NF    = 40;
constexpr int ED    = 64;
constexpr int NPAIR = NF * (NF - 1) / 2;   // 780
constexpr int NTILE = (NPAIR + 15) / 16;   // 49
constexpr int NPAD  = NTILE * 16;          // 784
constexpr int NT    = 256;
constexpr int XS    = 72;                  // sx row stride

__device__ __forceinline__ uint32_t pack_h2(float v0, float v1) {
    const __half2 h = __floats2half2_rn(v0, v1);   // .x = v0 (low half)
    return *(const uint32_t*)&h;
}
__device__ __forceinline__ void mma16816(float* c, const uint32_t* a,
                                         uint32_t b0, uint32_t b1) {
    asm volatile(
        "mma.sync.aligned.m16n8k16.row.col.f32.f16.f16.f32 "
        "{%0,%1,%2,%3}, {%4,%5,%6,%7}, {%8,%9}, {%0,%1,%2,%3};"
        : "+f"(c[0]), "+f"(c[1]), "+f"(c[2]), "+f"(c[3])
        : "r"(a[0]), "r"(a[1]), "r"(a[2]), "r"(a[3]), "r"(b0), "r"(b1));
}

__global__ __launch_bounds__(NT, 2)
void afm_mma_kernel(const float* __restrict__ x,
                    const float* __restrict__ W1,
                    const float* __restrict__ b1,
                    const float* __restrict__ W2,
                    const float* __restrict__ b2,
                    const float* __restrict__ Wl,
                    const float* __restrict__ bl,
                    float* __restrict__ out)
{
    __shared__ __align__(16) float    sx[NF * XS];
    __shared__           uint32_t sW1h[ED][36];   // staging for B frag load
    __shared__ __align__(16) float    sWl[ED];
    __shared__ __align__(16) float4   sEpi[32];   // (b1,W2,b1,W2) per (n,t)
    __shared__           float    logits[NPAD];
    __shared__           float    svals[NPAD];
    __shared__           uint32_t pairs[NPAD];
    __shared__           float    red[24];
    __shared__           float    scal1[1];

    const int tid = threadIdx.x;
    const int wid = tid >> 5, lid = tid & 31;
    const int gid = lid >> 2, t = lid & 3;
    const int b = blockIdx.x;

    // ---- stage x[b] ----
    const float* xb = x + (long)b * NF * ED;
    for (int i = tid; i < NF * ED; i += NT) sx[(i >> 6) * XS + (i & 63)] = xb[i];

    // ---- stage W1 (fp16 rounded), K-permuted packing ----
    // word w = kk*8 + q*4 + t holds W1[h][e0..e0+1], e0 = kk*16 + 4t + 2q
    for (int i = tid; i < ED * 32; i += NT) {
        const int h = i >> 5, w = i & 31;
        const int kk = w >> 3, q = (w >> 2) & 1, tt = w & 3;
        const int e0 = kk * 16 + 4 * tt + 2 * q;
        sW1h[h][w] = pack_h2(W1[h * 64 + e0], W1[h * 64 + e0 + 1]);
    }
    if (tid < 64) sWl[tid] = Wl[tid];
    if (tid < 32) {
        const int n = tid >> 2, tt = tid & 3;
        const int h0 = n * 8 + 2 * tt;
        sEpi[tid] = make_float4(b1[h0], W2[h0], b1[h0 + 1], W2[h0 + 1]);
    }
    if (tid == 0) scal1[0] = bl[0];

    // ---- pair index table ----
    for (int p = tid; p < NPAD; p += NT) {
        if (p < NPAIR) {
            int r = 0, rem = p;
            while (rem >= NF - 1 - r) { rem -= NF - 1 - r; ++r; }
            pairs[p] = ((uint32_t)r << 8) | (uint32_t)(r + 1 + rem);
        } else {
            pairs[p] = 1u;  // dummy (0,1)
        }
    }
    __syncthreads();

    const float blv = scal1[0];

    // ---- load ALL B fragments into registers (whole W1, warp-wide) ----
    uint32_t bf[8][4][2];
    #pragma unroll
    for (int n = 0; n < 8; ++n) {
        const uint32_t* rowH = sW1h[n * 8 + gid];
        #pragma unroll
        for (int kk = 0; kk < 4; ++kk) {
            bf[n][kk][0] = rowH[kk * 8 + t];
            bf[n][kk][1] = rowH[kk * 8 + 4 + t];
        }
    }

    for (int tile = wid; tile < NTILE; tile += 8) {
        const int p0 = tile * 16 + gid;

        const uint32_t rc0 = pairs[p0], rc1 = pairs[p0 + 8];
        const float* xr0 = sx + (rc0 >> 8) * XS;
        const float* xc0 = sx + (rc0 & 255u) * XS;
        const float* xr1 = sx + (rc1 >> 8) * XS;
        const float* xc1 = sx + (rc1 & 255u) * XS;

        float acc[8][4];
        #pragma unroll
        for (int n = 0; n < 8; ++n)
            acc[n][0] = acc[n][1] = acc[n][2] = acc[n][3] = 0.f;

        float s0 = 0.f, s1 = 0.f;
        #pragma unroll
        for (int kk = 0; kk < 4; ++kk) {
            // ---- A frags for this kk (transient, fp16-rounded) + s_p ----
            const int e = kk * 16 + 4 * t;
            const float4 wl = *(const float4*)&sWl[e];
            float4 a, c;
            a = *(const float4*)(xr0 + e); c = *(const float4*)(xc0 + e);
            const float v0 = a.x * c.x, v1 = a.y * c.y;
            const float v2 = a.z * c.z, v3 = a.w * c.w;
            a = *(const float4*)(xr1 + e); c = *(const float4*)(xc1 + e);
            const float v4 = a.x * c.x, v5 = a.y * c.y;
            const float v6 = a.z * c.z, v7 = a.w * c.w;

            s0 = fmaf(v0, wl.x, s0); s0 = fmaf(v1, wl.y, s0);
            s0 = fmaf(v2, wl.z, s0); s0 = fmaf(v3, wl.w, s0);
            s1 = fmaf(v4, wl.x, s1); s1 = fmaf(v5, wl.y, s1);
            s1 = fmaf(v6, wl.z, s1); s1 = fmaf(v7, wl.w, s1);

            uint32_t ra[4];
            ra[0] = pack_h2(v0, v1);
            ra[1] = pack_h2(v4, v5);
            ra[2] = pack_h2(v2, v3);
            ra[3] = pack_h2(v6, v7);

            // ---- 8 MMAs into 8 independent acc chains ----
            #pragma unroll
            for (int n = 0; n < 8; ++n)
                mma16816(acc[n], ra, bf[n][kk][0], bf[n][kk][1]);
        }

        // quad-reduce s_p
        s0 += __shfl_xor_sync(0xffffffffu, s0, 1);
        s0 += __shfl_xor_sync(0xffffffffu, s0, 2);
        s1 += __shfl_xor_sync(0xffffffffu, s1, 1);
        s1 += __shfl_xor_sync(0xffffffffu, s1, 2);
        if (t == 0) { svals[p0] = s0; svals[p0 + 8] = s1; }

        // ---- fused epilogue ----
        float lg0 = 0.f, lg1 = 0.f;
        #pragma unroll
        for (int n = 0; n < 8; ++n) {
            const float4 ep = sEpi[n * 4 + t];
            lg0 = fmaf(fmaxf(acc[n][0] + ep.x, 0.f), ep.y,
                  fmaf(fmaxf(acc[n][1] + ep.z, 0.f), ep.w, lg0));
            lg1 = fmaf(fmaxf(acc[n][2] + ep.x, 0.f), ep.y,
                  fmaf(fmaxf(acc[n][3] + ep.z, 0.f), ep.w, lg1));
        }
        lg0 += __shfl_xor_sync(0xffffffffu, lg0, 1);
        lg0 += __shfl_xor_sync(0xffffffffu, lg0, 2);
        lg1 += __shfl_xor_sync(0xffffffffu, lg1, 1);
        lg1 += __shfl_xor_sync(0xffffffffu, lg1, 2);
        if (t == 0) { logits[p0] = lg0; logits[p0 + 8] = lg1; }
    }
    __syncthreads();

    // ---- block-wide online softmax over 780 pairs ----
    float m = -FLT_MAX, Z = 0.f, S = 0.f;
    for (int p = tid; p < NPAIR; p += NT) {
        const float l = logits[p];
        const float s = svals[p];
        const float mn = fmaxf(m, l);
        const float sc = __expf(m - mn);
        const float w  = __expf(l - mn);
        Z = Z * sc + w;
        S = S * sc + s * w;
        m = mn;
    }
    #pragma unroll
    for (int off = 16; off; off >>= 1) {
        const float m2 = __shfl_down_sync(0xffffffffu, m, off);
        const float Z2 = __shfl_down_sync(0xffffffffu, Z, off);
        const float S2 = __shfl_down_sync(0xffffffffu, S, off);
        const float mn = fmaxf(m, m2);
        const float e1 = __expf(m - mn);
        const float e2 = __expf(m2 - mn);
        Z = Z * e1 + Z2 * e2;
        S = S * e1 + S2 * e2;
        m = mn;
    }
    if (lid == 0) { red[wid] = m; red[8 + wid] = Z; red[16 + wid] = S; }
    __syncthreads();
    if (wid == 0) {
        m = (lid < 8) ? red[lid] : -FLT_MAX;
        Z = (lid < 8) ? red[8 + lid] : 0.f;
        S = (lid < 8) ? red[16 + lid] : 0.f;
        #pragma unroll
        for (int off = 4; off; off >>= 1) {
            const float m2 = __shfl_down_sync(0xffffffffu, m, off);
            const float Z2 = __shfl_down_sync(0xffffffffu, Z, off);
            const float S2 = __shfl_down_sync(0xffffffffu, S, off);
            const float mn = fmaxf(m, m2);
            const float e1 = __expf(m - mn);
            const float e2 = __expf(m2 - mn);
            Z = Z * e1 + Z2 * e2;
            S = S * e1 + S2 * e2;
            m = mn;
        }
        if (lid == 0) out[b] = S / Z + blv;
    }
}

}  // namespace

extern "C" void kernel_launch(void* const* d_in, const int* in_sizes, int n_in,
                              void* d_out, int out_size)
{
    const float* x  = (const float*)d_in[0];
    const float* W1 = (const float*)d_in[1];
    const float* b1 = (const float*)d_in[2];
    const float* W2 = (const float*)d_in[3];
    const float* b2 = (const float*)d_in[4];
    const float* Wl = (const float*)d_in[5];
    const float* bl = (const float*)d_in[6];
    float* out = (float*)d_out;

    const int batch = in_sizes[0] / (NF * ED);  // 2048
    afm_mma_kernel<<<batch, NT>>>(x, W1, b1, W2, b2, Wl, bl, out);
}

// round 9
// speedup vs baseline: 6.0437x; 1.3310x over previous
#include <cuda_runtime.h>
#include <cuda_fp16.h>
#include <cstdint>
#include <float.h>

// AFM fused kernel — fp16 single-term mma.sync, W1 register-resident,
// fp16 x staging (half2 gather + f16x2 products), closed-form pair decode.
//
// out[b] = bl + sum_p softmax_p(l_p) * s_p
//   inner_p = rn16(x[b,r])∘rn16(x[b,c])   (f16x2 products = A fragments)
//   s_p = inner_p·Wl                      (fp32 dot of the same products)
//   l_p = W2·relu(W1·inner_p + b1)        (+b2 dropped: shift-invariant)
//
// W1 (64x64 fp16) entirely in registers (64/thread warp-wide).
// Per 16-pair tile: kk-outer half2 gather -> 4 f16x2 muls = A frags,
// 8 MMAs/kk into 8 independent acc chains; fused epilogue; block softmax.

namespace {

constexpr int NF    = 40;
constexpr int ED    = 64;
constexpr int NPAIR = NF * (NF - 1) / 2;   // 780
constexpr int NTILE = (NPAIR + 15) / 16;   // 49
constexpr int NPAD  = NTILE * 16;          // 784
constexpr int NT    = 256;
constexpr int ST2   = 36;                  // sx2 row stride in u32 (half2) words

__device__ __forceinline__ uint32_t pack_h2(float v0, float v1) {
    const __half2 h = __floats2half2_rn(v0, v1);   // .x = v0 (low half)
    return *(const uint32_t*)&h;
}
__device__ __forceinline__ uint32_t h2mul(uint32_t a, uint32_t b) {
    uint32_t d;
    asm("mul.rn.f16x2 %0, %1, %2;" : "=r"(d) : "r"(a), "r"(b));
    return d;
}
__device__ __forceinline__ float2 h2f2(uint32_t u) {
    return __half22float2(*reinterpret_cast<const __half2*>(&u));
}
__device__ __forceinline__ void mma16816(float* c, const uint32_t* a,
                                         uint32_t b0, uint32_t b1) {
    asm volatile(
        "mma.sync.aligned.m16n8k16.row.col.f32.f16.f16.f32 "
        "{%0,%1,%2,%3}, {%4,%5,%6,%7}, {%8,%9}, {%0,%1,%2,%3};"
        : "+f"(c[0]), "+f"(c[1]), "+f"(c[2]), "+f"(c[3])
        : "r"(a[0]), "r"(a[1]), "r"(a[2]), "r"(a[3]), "r"(b0), "r"(b1));
}

// pair index p -> (row<<8)|col for upper-triangle k=1, NF=40.
__device__ __forceinline__ uint32_t decode_pair(int p) {
    const float d = sqrtf(6241.0f - 8.0f * (float)p);
    int r = __float2int_rd((79.0f - d) * 0.5f);
    if (r * (79 - r) / 2 > p) --r;
    if ((r + 1) * (78 - r) / 2 <= p) ++r;
    const int c = p - r * (79 - r) / 2 + r + 1;
    return ((uint32_t)r << 8) | (uint32_t)c;
}

__global__ __launch_bounds__(NT, 2)
void afm_mma_kernel(const float* __restrict__ x,
                    const float* __restrict__ W1,
                    const float* __restrict__ b1,
                    const float* __restrict__ W2,
                    const float* __restrict__ b2,
                    const float* __restrict__ Wl,
                    const float* __restrict__ bl,
                    float* __restrict__ out)
{
    __shared__ __align__(8)  uint32_t sx2[NF * ST2];  // half2-packed x rows
    __shared__           uint32_t sW1h[ED][36];       // staging for B frag load
    __shared__ __align__(16) float    sWl[ED];
    __shared__ __align__(16) float4   sEpi[32];       // (b1,W2,b1,W2) per (n,t)
    __shared__           float    logits[NPAD];
    __shared__           float    svals[NPAD];
    __shared__           float    red[24];
    __shared__           float    scal1[1];

    const int tid = threadIdx.x;
    const int wid = tid >> 5, lid = tid & 31;
    const int gid = lid >> 2, t = lid & 3;
    const int b = blockIdx.x;

    // ---- stage x[b] as half2 (one rounding; GEMM and s_p share it) ----
    const float4* xb4 = (const float4*)(x + (long)b * NF * ED);
    for (int i = tid; i < NF * ED / 4; i += NT) {
        const float4 v = xb4[i];
        const int row = i >> 4, j = i & 15;          // 16 float4 per row
        sx2[row * ST2 + 2 * j]     = pack_h2(v.x, v.y);
        sx2[row * ST2 + 2 * j + 1] = pack_h2(v.z, v.w);
    }

    // ---- stage W1 (fp16 rounded), K-permuted packing ----
    // word w = kk*8 + q*4 + t holds W1[h][e0..e0+1], e0 = kk*16 + 4t + 2q
    for (int i = tid; i < ED * 32; i += NT) {
        const int h = i >> 5, w = i & 31;
        const int kk = w >> 3, q = (w >> 2) & 1, tt = w & 3;
        const int e0 = kk * 16 + 4 * tt + 2 * q;
        sW1h[h][w] = pack_h2(W1[h * 64 + e0], W1[h * 64 + e0 + 1]);
    }
    if (tid < 64) sWl[tid] = Wl[tid];
    if (tid < 32) {
        const int n = tid >> 2, tt = tid & 3;
        const int h0 = n * 8 + 2 * tt;
        sEpi[tid] = make_float4(b1[h0], W2[h0], b1[h0 + 1], W2[h0 + 1]);
    }
    if (tid == 0) scal1[0] = bl[0];
    __syncthreads();

    const float blv = scal1[0];

    // ---- load ALL B fragments into registers (whole W1, warp-wide) ----
    uint32_t bf[8][4][2];
    #pragma unroll
    for (int n = 0; n < 8; ++n) {
        const uint32_t* rowH = sW1h[n * 8 + gid];
        #pragma unroll
        for (int kk = 0; kk < 4; ++kk) {
            bf[n][kk][0] = rowH[kk * 8 + t];
            bf[n][kk][1] = rowH[kk * 8 + 4 + t];
        }
    }

    for (int tile = wid; tile < NTILE; tile += 8) {
        const int p0 = tile * 16 + gid;
        const int pc0 = p0 < NPAIR ? p0 : NPAIR - 1;
        const int pc1 = (p0 + 8) < NPAIR ? (p0 + 8) : NPAIR - 1;

        const uint32_t rc0 = decode_pair(pc0);
        const uint32_t rc1 = decode_pair(pc1);
        const uint32_t* xr0 = sx2 + (rc0 >> 8) * ST2;
        const uint32_t* xc0 = sx2 + (rc0 & 255u) * ST2;
        const uint32_t* xr1 = sx2 + (rc1 >> 8) * ST2;
        const uint32_t* xc1 = sx2 + (rc1 & 255u) * ST2;

        float acc[8][4];
        #pragma unroll
        for (int n = 0; n < 8; ++n)
            acc[n][0] = acc[n][1] = acc[n][2] = acc[n][3] = 0.f;

        float s0 = 0.f, s1 = 0.f;
        #pragma unroll
        for (int kk = 0; kk < 4; ++kk) {
            const int base = kk * 8 + 2 * t;          // half2 word offset
            const float4 wl = *(const float4*)&sWl[kk * 16 + 4 * t];

            const uint2 a0 = *(const uint2*)(xr0 + base);
            const uint2 c0 = *(const uint2*)(xc0 + base);
            const uint2 a1 = *(const uint2*)(xr1 + base);
            const uint2 c1 = *(const uint2*)(xc1 + base);

            uint32_t ra[4];
            ra[0] = h2mul(a0.x, c0.x);   // pair0, elems e..e+1
            ra[2] = h2mul(a0.y, c0.y);   // pair0, elems e+2..e+3
            ra[1] = h2mul(a1.x, c1.x);   // pair1, elems e..e+1
            ra[3] = h2mul(a1.y, c1.y);   // pair1, elems e+2..e+3

            // s_p partials from the SAME rounded products (fp32)
            const float2 f00 = h2f2(ra[0]);
            const float2 f02 = h2f2(ra[2]);
            const float2 f10 = h2f2(ra[1]);
            const float2 f12 = h2f2(ra[3]);
            s0 = fmaf(f00.x, wl.x, s0); s0 = fmaf(f00.y, wl.y, s0);
            s0 = fmaf(f02.x, wl.z, s0); s0 = fmaf(f02.y, wl.w, s0);
            s1 = fmaf(f10.x, wl.x, s1); s1 = fmaf(f10.y, wl.y, s1);
            s1 = fmaf(f12.x, wl.z, s1); s1 = fmaf(f12.y, wl.w, s1);

            // ---- 8 MMAs into 8 independent acc chains ----
            #pragma unroll
            for (int n = 0; n < 8; ++n)
                mma16816(acc[n], ra, bf[n][kk][0], bf[n][kk][1]);
        }

        // quad-reduce s_p
        s0 += __shfl_xor_sync(0xffffffffu, s0, 1);
        s0 += __shfl_xor_sync(0xffffffffu, s0, 2);
        s1 += __shfl_xor_sync(0xffffffffu, s1, 1);
        s1 += __shfl_xor_sync(0xffffffffu, s1, 2);
        if (t == 0) { svals[p0] = s0; svals[p0 + 8] = s1; }

        // ---- fused epilogue ----
        float lg0 = 0.f, lg1 = 0.f;
        #pragma unroll
        for (int n = 0; n < 8; ++n) {
            const float4 ep = sEpi[n * 4 + t];
            lg0 = fmaf(fmaxf(acc[n][0] + ep.x, 0.f), ep.y,
                  fmaf(fmaxf(acc[n][1] + ep.z, 0.f), ep.w, lg0));
            lg1 = fmaf(fmaxf(acc[n][2] + ep.x, 0.f), ep.y,
                  fmaf(fmaxf(acc[n][3] + ep.z, 0.f), ep.w, lg1));
        }
        lg0 += __shfl_xor_sync(0xffffffffu, lg0, 1);
        lg0 += __shfl_xor_sync(0xffffffffu, lg0, 2);
        lg1 += __shfl_xor_sync(0xffffffffu, lg1, 1);
        lg1 += __shfl_xor_sync(0xffffffffu, lg1, 2);
        if (t == 0) { logits[p0] = lg0; logits[p0 + 8] = lg1; }
    }
    __syncthreads();

    // ---- block-wide online softmax over 780 pairs ----
    float m = -FLT_MAX, Z = 0.f, S = 0.f;
    for (int p = tid; p < NPAIR; p += NT) {
        const float l = logits[p];
        const float s = svals[p];
        const float mn = fmaxf(m, l);
        const float sc = __expf(m - mn);
        const float w  = __expf(l - mn);
        Z = Z * sc + w;
        S = S * sc + s * w;
        m = mn;
    }
    #pragma unroll
    for (int off = 16; off; off >>= 1) {
        const float m2 = __shfl_down_sync(0xffffffffu, m, off);
        const float Z2 = __shfl_down_sync(0xffffffffu, Z, off);
        const float S2 = __shfl_down_sync(0xffffffffu, S, off);
        const float mn = fmaxf(m, m2);
        const float e1 = __expf(m - mn);
        const float e2 = __expf(m2 - mn);
        Z = Z * e1 + Z2 * e2;
        S = S * e1 + S2 * e2;
        m = mn;
    }
    if (lid == 0) { red[wid] = m; red[8 + wid] = Z; red[16 + wid] = S; }
    __syncthreads();
    if (wid == 0) {
        m = (lid < 8) ? red[lid] : -FLT_MAX;
        Z = (lid < 8) ? red[8 + lid] : 0.f;
        S = (lid < 8) ? red[16 + lid] : 0.f;
        #pragma unroll
        for (int off = 4; off; off >>= 1) {
            const float m2 = __shfl_down_sync(0xffffffffu, m, off);
            const float Z2 = __shfl_down_sync(0xffffffffu, Z, off);
            const float S2 = __shfl_down_sync(0xffffffffu, S, off);
            const float mn = fmaxf(m, m2);
            const float e1 = __expf(m - mn);
            const float e2 = __expf(m2 - mn);
            Z = Z * e1 + Z2 * e2;
            S = S * e1 + S2 * e2;
            m = mn;
        }
        if (lid == 0) out[b] = S / Z + blv;
    }
}

}  // namespace

extern "C" void kernel_launch(void* const* d_in, const int* in_sizes, int n_in,
                              void* d_out, int out_size)
{
    const float* x  = (const float*)d_in[0];
    const float* W1 = (const float*)d_in[1];
    const float* b1 = (const float*)d_in[2];
    const float* W2 = (const float*)d_in[3];
    const float* b2 = (const float*)d_in[4];
    const float* Wl = (const float*)d_in[5];
    const float* bl = (const float*)d_in[6];
    float* out = (float*)d_out;

    const int batch = in_sizes[0] / (NF * ED);  // 2048
    afm_mma_kernel<<<batch, NT>>>(x, W1, b1, W2, b2, Wl, bl, out);
}

// round 10
// speedup vs baseline: 6.4404x; 1.0656x over previous
#include <cuda_runtime.h>
#include <cuda_fp16.h>
#include <cstdint>
#include <float.h>

// AFM fused kernel — fp16 single-term mma.sync, W1 register-resident,
// fp16 x staging, s_p folded into an extra MMA column (Wl as B col 0).
//
// out[b] = bl + sum_p softmax_p(l_p) * s_p
//   inner_p = rn16(x[b,r])∘rn16(x[b,c])   (f16x2 products = A fragments)
//   s_p = inner_p·rn16(Wl)                (extra m16n8k16, fp32 accum)
//   l_p = W2·relu(W1·inner_p + b1)        (+b2 dropped: shift-invariant)
//
// W1 (64x64 fp16) entirely in registers (64/thread warp-wide); Wl fragment
// nonzero only in gid==0 lanes (B column 0). Per 16-pair tile: kk-outer
// half2 gather -> 4 f16x2 muls = A frags, 9 MMAs/kk (8 W1 + 1 Wl) into
// 9 independent acc chains; fused epilogue; block softmax.

namespace {

constexpr int NF    = 40;
constexpr int ED    = 64;
constexpr int NPAIR = NF * (NF - 1) / 2;   // 780
constexpr int NTILE = (NPAIR + 15) / 16;   // 49
constexpr int NPAD  = NTILE * 16;          // 784
constexpr int NT    = 256;
constexpr int ST2   = 36;                  // sx2 row stride in u32 (half2) words

__device__ __forceinline__ uint32_t pack_h2(float v0, float v1) {
    const __half2 h = __floats2half2_rn(v0, v1);   // .x = v0 (low half)
    return *(const uint32_t*)&h;
}
__device__ __forceinline__ uint32_t h2mul(uint32_t a, uint32_t b) {
    uint32_t d;
    asm("mul.rn.f16x2 %0, %1, %2;" : "=r"(d) : "r"(a), "r"(b));
    return d;
}
__device__ __forceinline__ void mma16816(float* c, const uint32_t* a,
                                         uint32_t b0, uint32_t b1) {
    asm volatile(
        "mma.sync.aligned.m16n8k16.row.col.f32.f16.f16.f32 "
        "{%0,%1,%2,%3}, {%4,%5,%6,%7}, {%8,%9}, {%0,%1,%2,%3};"
        : "+f"(c[0]), "+f"(c[1]), "+f"(c[2]), "+f"(c[3])
        : "r"(a[0]), "r"(a[1]), "r"(a[2]), "r"(a[3]), "r"(b0), "r"(b1));
}

// pair index p -> (row<<8)|col for upper-triangle k=1, NF=40.
__device__ __forceinline__ uint32_t decode_pair(int p) {
    const float d = sqrtf(6241.0f - 8.0f * (float)p);
    int r = __float2int_rd((79.0f - d) * 0.5f);
    if (r * (79 - r) / 2 > p) --r;
    if ((r + 1) * (78 - r) / 2 <= p) ++r;
    const int c = p - r * (79 - r) / 2 + r + 1;
    return ((uint32_t)r << 8) | (uint32_t)c;
}

__global__ __launch_bounds__(NT, 2)
void afm_mma_kernel(const float* __restrict__ x,
                    const float* __restrict__ W1,
                    const float* __restrict__ b1,
                    const float* __restrict__ W2,
                    const float* __restrict__ b2,
                    const float* __restrict__ Wl,
                    const float* __restrict__ bl,
                    float* __restrict__ out)
{
    __shared__ __align__(8)  uint32_t sx2[NF * ST2];  // half2-packed x rows
    __shared__           uint32_t sW1h[ED][36];       // staging for B frag load
    __shared__ __align__(16) float4   sEpi[32];       // (b1,W2,b1,W2) per (n,t)
    __shared__           float    logits[NPAD];
    __shared__           float    svals[NPAD];
    __shared__           float    red[24];
    __shared__           float    scal1[1];

    const int tid = threadIdx.x;
    const int wid = tid >> 5, lid = tid & 31;
    const int gid = lid >> 2, t = lid & 3;
    const int b = blockIdx.x;

    // ---- stage x[b] as half2 (one rounding; GEMM and s_p share it) ----
    const float4* xb4 = (const float4*)(x + (long)b * NF * ED);
    for (int i = tid; i < NF * ED / 4; i += NT) {
        const float4 v = xb4[i];
        const int row = i >> 4, j = i & 15;          // 16 float4 per row
        sx2[row * ST2 + 2 * j]     = pack_h2(v.x, v.y);
        sx2[row * ST2 + 2 * j + 1] = pack_h2(v.z, v.w);
    }

    // ---- stage W1 (fp16 rounded), K-permuted packing ----
    // word w = kk*8 + q*4 + t holds W1[h][e0..e0+1], e0 = kk*16 + 4t + 2q
    for (int i = tid; i < ED * 32; i += NT) {
        const int h = i >> 5, w = i & 31;
        const int kk = w >> 3, q = (w >> 2) & 1, tt = w & 3;
        const int e0 = kk * 16 + 4 * tt + 2 * q;
        sW1h[h][w] = pack_h2(W1[h * 64 + e0], W1[h * 64 + e0 + 1]);
    }
    if (tid < 32) {
        const int n = tid >> 2, tt = tid & 3;
        const int h0 = n * 8 + 2 * tt;
        sEpi[tid] = make_float4(b1[h0], W2[h0], b1[h0 + 1], W2[h0 + 1]);
    }
    if (tid == 0) scal1[0] = bl[0];

    // ---- Wl B-fragment (column 0 only): nonzero in gid==0 lanes ----
    // wlf[kk][0] covers k = kk*16 + 4t + {0,1}; wlf[kk][1] covers +{2,3}.
    uint32_t wlf[4][2] = {{0u,0u},{0u,0u},{0u,0u},{0u,0u}};
    if (gid == 0) {
        #pragma unroll
        for (int kk = 0; kk < 4; ++kk) {
            const int e = kk * 16 + 4 * t;
            wlf[kk][0] = pack_h2(Wl[e],     Wl[e + 1]);
            wlf[kk][1] = pack_h2(Wl[e + 2], Wl[e + 3]);
        }
    }
    __syncthreads();

    const float blv = scal1[0];

    // ---- load ALL B fragments into registers (whole W1, warp-wide) ----
    uint32_t bf[8][4][2];
    #pragma unroll
    for (int n = 0; n < 8; ++n) {
        const uint32_t* rowH = sW1h[n * 8 + gid];
        #pragma unroll
        for (int kk = 0; kk < 4; ++kk) {
            bf[n][kk][0] = rowH[kk * 8 + t];
            bf[n][kk][1] = rowH[kk * 8 + 4 + t];
        }
    }

    for (int tile = wid; tile < NTILE; tile += 8) {
        const int p0 = tile * 16 + gid;
        const int pc0 = p0 < NPAIR ? p0 : NPAIR - 1;
        const int pc1 = (p0 + 8) < NPAIR ? (p0 + 8) : NPAIR - 1;

        const uint32_t rc0 = decode_pair(pc0);
        const uint32_t rc1 = decode_pair(pc1);
        const uint32_t* xr0 = sx2 + (rc0 >> 8) * ST2;
        const uint32_t* xc0 = sx2 + (rc0 & 255u) * ST2;
        const uint32_t* xr1 = sx2 + (rc1 >> 8) * ST2;
        const uint32_t* xc1 = sx2 + (rc1 & 255u) * ST2;

        float acc[8][4];
        #pragma unroll
        for (int n = 0; n < 8; ++n)
            acc[n][0] = acc[n][1] = acc[n][2] = acc[n][3] = 0.f;
        float accs[4] = {0.f, 0.f, 0.f, 0.f};

        #pragma unroll
        for (int kk = 0; kk < 4; ++kk) {
            const int base = kk * 8 + 2 * t;          // half2 word offset

            const uint2 a0 = *(const uint2*)(xr0 + base);
            const uint2 c0 = *(const uint2*)(xc0 + base);
            const uint2 a1 = *(const uint2*)(xr1 + base);
            const uint2 c1 = *(const uint2*)(xc1 + base);

            uint32_t ra[4];
            ra[0] = h2mul(a0.x, c0.x);   // pair0, elems e..e+1
            ra[2] = h2mul(a0.y, c0.y);   // pair0, elems e+2..e+3
            ra[1] = h2mul(a1.x, c1.x);   // pair1, elems e..e+1
            ra[3] = h2mul(a1.y, c1.y);   // pair1, elems e+2..e+3

            // ---- 9 MMAs into 9 independent acc chains ----
            mma16816(accs, ra, wlf[kk][0], wlf[kk][1]);
            #pragma unroll
            for (int n = 0; n < 8; ++n)
                mma16816(acc[n], ra, bf[n][kk][0], bf[n][kk][1]);
        }

        // s_p sits in column 0 of accs: t==0 lanes, rows gid / gid+8
        if (t == 0) { svals[p0] = accs[0]; svals[p0 + 8] = accs[2]; }

        // ---- fused epilogue ----
        float lg0 = 0.f, lg1 = 0.f;
        #pragma unroll
        for (int n = 0; n < 8; ++n) {
            const float4 ep = sEpi[n * 4 + t];
            lg0 = fmaf(fmaxf(acc[n][0] + ep.x, 0.f), ep.y,
                  fmaf(fmaxf(acc[n][1] + ep.z, 0.f), ep.w, lg0));
            lg1 = fmaf(fmaxf(acc[n][2] + ep.x, 0.f), ep.y,
                  fmaf(fmaxf(acc[n][3] + ep.z, 0.f), ep.w, lg1));
        }
        lg0 += __shfl_xor_sync(0xffffffffu, lg0, 1);
        lg0 += __shfl_xor_sync(0xffffffffu, lg0, 2);
        lg1 += __shfl_xor_sync(0xffffffffu, lg1, 1);
        lg1 += __shfl_xor_sync(0xffffffffu, lg1, 2);
        if (t == 0) { logits[p0] = lg0; logits[p0 + 8] = lg1; }
    }
    __syncthreads();

    // ---- block-wide online softmax over 780 pairs ----
    float m = -FLT_MAX, Z = 0.f, S = 0.f;
    for (int p = tid; p < NPAIR; p += NT) {
        const float l = logits[p];
        const float s = svals[p];
        const float mn = fmaxf(m, l);
        const float sc = __expf(m - mn);
        const float w  = __expf(l - mn);
        Z = Z * sc + w;
        S = S * sc + s * w;
        m = mn;
    }
    #pragma unroll
    for (int off = 16; off; off >>= 1) {
        const float m2 = __shfl_down_sync(0xffffffffu, m, off);
        const float Z2 = __shfl_down_sync(0xffffffffu, Z, off);
        const float S2 = __shfl_down_sync(0xffffffffu, S, off);
        const float mn = fmaxf(m, m2);
        const float e1 = __expf(m - mn);
        const float e2 = __expf(m2 - mn);
        Z = Z * e1 + Z2 * e2;
        S = S * e1 + S2 * e2;
        m = mn;
    }
    if (lid == 0) { red[wid] = m; red[8 + wid] = Z; red[16 + wid] = S; }
    __syncthreads();
    if (wid == 0) {
        m = (lid < 8) ? red[lid] : -FLT_MAX;
        Z = (lid < 8) ? red[8 + lid] : 0.f;
        S = (lid < 8) ? red[16 + lid] : 0.f;
        #pragma unroll
        for (int off = 4; off; off >>= 1) {
            const float m2 = __shfl_down_sync(0xffffffffu, m, off);
            const float Z2 = __shfl_down_sync(0xffffffffu, Z, off);
            const float S2 = __shfl_down_sync(0xffffffffu, S, off);
            const float mn = fmaxf(m, m2);
            const float e1 = __expf(m - mn);
            const float e2 = __expf(m2 - mn);
            Z = Z * e1 + Z2 * e2;
            S = S * e1 + S2 * e2;
            m = mn;
        }
        if (lid == 0) out[b] = S / Z + blv;
    }
}

}  // namespace

extern "C" void kernel_launch(void* const* d_in, const int* in_sizes, int n_in,
                              void* d_out, int out_size)
{
    const float* x  = (const float*)d_in[0];
    const float* W1 = (const float*)d_in[1];
    const float* b1 = (const float*)d_in[2];
    const float* W2 = (const float*)d_in[3];
    const float* b2 = (const float*)d_in[4];
    const float* Wl = (const float*)d_in[5];
    const float* bl = (const float*)d_in[6];
    float* out = (float*)d_out;

    const int batch = in_sizes[0] / (NF * ED);  // 2048
    afm_mma_kernel<<<batch, NT>>>(x, W1, b1, W2, b2, Wl, bl, out);
}

// round 12
// speedup vs baseline: 6.9205x; 1.0746x over previous
#include <cuda_runtime.h>
#include <cuda_fp16.h>
#include <cstdint>
#include <float.h>

// AFM fused kernel — fp16 single-term mma.sync, W1 register-resident,
// fp16 x staging, s_p folded into an extra MMA column, TWO batches per CTA.
//
// out[b] = bl + sum_p softmax_p(l_p) * s_p
//   inner_p = rn16(x[b,r])∘rn16(x[b,c])   (f16x2 products = A fragments)
//   s_p = inner_p·rn16(Wl)                (extra m16n8k16, fp32 accum)
//   l_p = W2·relu(W1·inner_p + b1)        (+b2 dropped: shift-invariant)
//
// Each CTA handles batches 2b, 2b+1: shared W1 staging/B-frags, 98 tiles
// strided over 8 warps (2% imbalance vs 14% at 49/8). Final softmax: two
// independent 4-warp reductions.

namespace {

constexpr int NF    = 40;
constexpr int ED    = 64;
constexpr int NPAIR = NF * (NF - 1) / 2;   // 780
constexpr int NTILE = (NPAIR + 15) / 16;   // 49
constexpr int NPAD  = NTILE * 16;          // 784
constexpr int NT    = 256;
constexpr int ST2   = 36;                  // sx2 row stride in u32 (half2) words

__device__ __forceinline__ uint32_t pack_h2(float v0, float v1) {
    const __half2 h = __floats2half2_rn(v0, v1);   // .x = v0 (low half)
    return *(const uint32_t*)&h;
}
__device__ __forceinline__ uint32_t h2mul(uint32_t a, uint32_t b) {
    uint32_t d;
    asm("mul.rn.f16x2 %0, %1, %2;" : "=r"(d) : "r"(a), "r"(b));
    return d;
}
__device__ __forceinline__ void mma16816(float* c, const uint32_t* a,
                                         uint32_t b0, uint32_t b1) {
    asm volatile(
        "mma.sync.aligned.m16n8k16.row.col.f32.f16.f16.f32 "
        "{%0,%1,%2,%3}, {%4,%5,%6,%7}, {%8,%9}, {%0,%1,%2,%3};"
        : "+f"(c[0]), "+f"(c[1]), "+f"(c[2]), "+f"(c[3])
        : "r"(a[0]), "r"(a[1]), "r"(a[2]), "r"(a[3]), "r"(b0), "r"(b1));
}

// pair index p -> (row<<8)|col for upper-triangle k=1, NF=40.
__device__ __forceinline__ uint32_t decode_pair(int p) {
    const float d = sqrtf(6241.0f - 8.0f * (float)p);
    int r = __float2int_rd((79.0f - d) * 0.5f);
    if (r * (79 - r) / 2 > p) --r;
    if ((r + 1) * (78 - r) / 2 <= p) ++r;
    const int c = p - r * (79 - r) / 2 + r + 1;
    return ((uint32_t)r << 8) | (uint32_t)c;
}

__global__ __launch_bounds__(NT, 2)
void afm_mma_kernel(const float* __restrict__ x,
                    const float* __restrict__ W1,
                    const float* __restrict__ b1,
                    const float* __restrict__ W2,
                    const float* __restrict__ b2,
                    const float* __restrict__ Wl,
                    const float* __restrict__ bl,
                    float* __restrict__ out)
{
    __shared__ __align__(8)  uint32_t sx2[2 * NF * ST2];  // rows 0-39: b0, 40-79: b1
    __shared__           uint32_t sW1h[ED][36];           // staging for B frag load
    __shared__ __align__(16) float4   sEpi[32];           // (b1,W2,b1,W2) per (n,t)
    __shared__           float    logits[2 * NPAD];
    __shared__           float    svals[2 * NPAD];
    __shared__           float    red[24];
    __shared__           float    scal1[1];

    const int tid = threadIdx.x;
    const int wid = tid >> 5, lid = tid & 31;
    const int gid = lid >> 2, t = lid & 3;
    const int b = blockIdx.x;                 // handles batches 2b, 2b+1

    // ---- stage x for BOTH batches (contiguous in gmem) as half2 ----
    const float4* xb4 = (const float4*)(x + (long)(2 * b) * NF * ED);
    for (int i = tid; i < 2 * NF * ED / 4; i += NT) {   // 1280 float4
        const float4 v = xb4[i];
        const int row = i >> 4, j = i & 15;             // row in [0,80)
        sx2[row * ST2 + 2 * j]     = pack_h2(v.x, v.y);
        sx2[row * ST2 + 2 * j + 1] = pack_h2(v.z, v.w);
    }

    // ---- stage W1 (fp16 rounded), K-permuted packing ----
    // word w = kk*8 + q*4 + t holds W1[h][e0..e0+1], e0 = kk*16 + 4t + 2q
    for (int i = tid; i < ED * 32; i += NT) {
        const int h = i >> 5, w = i & 31;
        const int kk = w >> 3, q = (w >> 2) & 1, tt = w & 3;
        const int e0 = kk * 16 + 4 * tt + 2 * q;
        sW1h[h][w] = pack_h2(W1[h * 64 + e0], W1[h * 64 + e0 + 1]);
    }
    if (tid < 32) {
        const int n = tid >> 2, tt = tid & 3;
        const int h0 = n * 8 + 2 * tt;
        sEpi[tid] = make_float4(b1[h0], W2[h0], b1[h0 + 1], W2[h0 + 1]);
    }
    if (tid == 0) scal1[0] = bl[0];

    // ---- Wl B-fragment (column 0 only): nonzero in gid==0 lanes ----
    uint32_t wlf[4][2] = {{0u,0u},{0u,0u},{0u,0u},{0u,0u}};
    if (gid == 0) {
        #pragma unroll
        for (int kk = 0; kk < 4; ++kk) {
            const int e = kk * 16 + 4 * t;
            wlf[kk][0] = pack_h2(Wl[e],     Wl[e + 1]);
            wlf[kk][1] = pack_h2(Wl[e + 2], Wl[e + 3]);
        }
    }
    __syncthreads();

    const float blv = scal1[0];

    // ---- load ALL B fragments into registers (whole W1, warp-wide) ----
    uint32_t bf[8][4][2];
    #pragma unroll
    for (int n = 0; n < 8; ++n) {
        const uint32_t* rowH = sW1h[n * 8 + gid];
        #pragma unroll
        for (int kk = 0; kk < 4; ++kk) {
            bf[n][kk][0] = rowH[kk * 8 + t];
            bf[n][kk][1] = rowH[kk * 8 + 4 + t];
        }
    }

    // ---- main loop: 98 tiles (2 batches x 49) over 8 warps ----
    for (int tile = wid; tile < 2 * NTILE; tile += 8) {
        const int bt = (tile >= NTILE) ? 1 : 0;
        const int tl = tile - bt * NTILE;
        const int p0 = tl * 16 + gid;
        const int pc0 = p0 < NPAIR ? p0 : NPAIR - 1;
        const int pc1 = (p0 + 8) < NPAIR ? (p0 + 8) : NPAIR - 1;

        const uint32_t* sxb = sx2 + bt * (NF * ST2);
        const uint32_t rc0 = decode_pair(pc0);
        const uint32_t rc1 = decode_pair(pc1);
        const uint32_t* xr0 = sxb + (rc0 >> 8) * ST2;
        const uint32_t* xc0 = sxb + (rc0 & 255u) * ST2;
        const uint32_t* xr1 = sxb + (rc1 >> 8) * ST2;
        const uint32_t* xc1 = sxb + (rc1 & 255u) * ST2;

        float acc[8][4];
        #pragma unroll
        for (int n = 0; n < 8; ++n)
            acc[n][0] = acc[n][1] = acc[n][2] = acc[n][3] = 0.f;
        float accs[4] = {0.f, 0.f, 0.f, 0.f};

        #pragma unroll
        for (int kk = 0; kk < 4; ++kk) {
            const int base = kk * 8 + 2 * t;          // half2 word offset

            const uint2 a0 = *(const uint2*)(xr0 + base);
            const uint2 c0 = *(const uint2*)(xc0 + base);
            const uint2 a1 = *(const uint2*)(xr1 + base);
            const uint2 c1 = *(const uint2*)(xc1 + base);

            uint32_t ra[4];
            ra[0] = h2mul(a0.x, c0.x);
            ra[2] = h2mul(a0.y, c0.y);
            ra[1] = h2mul(a1.x, c1.x);
            ra[3] = h2mul(a1.y, c1.y);

            mma16816(accs, ra, wlf[kk][0], wlf[kk][1]);
            #pragma unroll
            for (int n = 0; n < 8; ++n)
                mma16816(acc[n], ra, bf[n][kk][0], bf[n][kk][1]);
        }

        const int ob = bt * NPAD + p0;
        if (t == 0) { svals[ob] = accs[0]; svals[ob + 8] = accs[2]; }

        // ---- fused epilogue ----
        float lg0 = 0.f, lg1 = 0.f;
        #pragma unroll
        for (int n = 0; n < 8; ++n) {
            const float4 ep = sEpi[n * 4 + t];
            lg0 = fmaf(fmaxf(acc[n][0] + ep.x, 0.f), ep.y,
                  fmaf(fmaxf(acc[n][1] + ep.z, 0.f), ep.w, lg0));
            lg1 = fmaf(fmaxf(acc[n][2] + ep.x, 0.f), ep.y,
                  fmaf(fmaxf(acc[n][3] + ep.z, 0.f), ep.w, lg1));
        }
        lg0 += __shfl_xor_sync(0xffffffffu, lg0, 1);
        lg0 += __shfl_xor_sync(0xffffffffu, lg0, 2);
        lg1 += __shfl_xor_sync(0xffffffffu, lg1, 1);
        lg1 += __shfl_xor_sync(0xffffffffu, lg1, 2);
        if (t == 0) { logits[ob] = lg0; logits[ob + 8] = lg1; }
    }
    __syncthreads();

    // ---- two independent 4-warp online-softmax reductions ----
    const int group = wid >> 2;     // batch this warp reduces
    const int gw = wid & 3;
    const float* lgp = logits + group * NPAD;
    const float* svp = svals + group * NPAD;

    float m = -FLT_MAX, Z = 0.f, S = 0.f;
    for (int p = gw * 32 + lid; p < NPAIR; p += 128) {
        const float l = lgp[p];
        const float s = svp[p];
        const float mn = fmaxf(m, l);
        const float sc = __expf(m - mn);
        const float w  = __expf(l - mn);
        Z = Z * sc + w;
        S = S * sc + s * w;
        m = mn;
    }
    #pragma unroll
    for (int off = 16; off; off >>= 1) {
        const float m2 = __shfl_down_sync(0xffffffffu, m, off);
        const float Z2 = __shfl_down_sync(0xffffffffu, Z, off);
        const float S2 = __shfl_down_sync(0xffffffffu, S, off);
        const float mn = fmaxf(m, m2);
        const float e1 = __expf(m - mn);
        const float e2 = __expf(m2 - mn);
        Z = Z * e1 + Z2 * e2;
        S = S * e1 + S2 * e2;
        m = mn;
    }
    if (lid == 0) {
        red[group * 12 + gw]     = m;
        red[group * 12 + 4 + gw] = Z;
        red[group * 12 + 8 + gw] = S;
    }
    __syncthreads();
    if (gw == 0) {
        m = (lid < 4) ? red[group * 12 + lid]     : -FLT_MAX;
        Z = (lid < 4) ? red[group * 12 + 4 + lid] : 0.f;
        S = (lid < 4) ? red[group * 12 + 8 + lid] : 0.f;
        #pragma unroll
        for (int off = 2; off; off >>= 1) {
            const float m2 = __shfl_down_sync(0xffffffffu, m, off);
            const float Z2 = __shfl_down_sync(0xffffffffu, Z, off);
            const float S2 = __shfl_down_sync(0xffffffffu, S, off);
            const float mn = fmaxf(m, m2);
            const float e1 = __expf(m - mn);
            const float e2 = __expf(m2 - mn);
            Z = Z * e1 + Z2 * e2;
            S = S * e1 + S2 * e2;
            m = mn;
        }
        if (lid == 0) out[2 * b + group] = S / Z + blv;
    }
}

}  // namespace

extern "C" void kernel_launch(void* const* d_in, const int* in_sizes, int n_in,
                              void* d_out, int out_size)
{
    const float* x  = (const float*)d_in[0];
    const float* W1 = (const float*)d_in[1];
    const float* b1 = (const float*)d_in[2];
    const float* W2 = (const float*)d_in[3];
    const float* b2 = (const float*)d_in[4];
    const float* Wl = (const float*)d_in[5];
    const float* bl = (const float*)d_in[6];
    float* out = (float*)d_out;

    const int batch = in_sizes[0] / (NF * ED);  // 2048
    afm_mma_kernel<<<batch / 2, NT>>>(x, W1, b1, W2, b2, Wl, bl, out);
}